// round 9
// baseline (speedup 1.0000x reference)
#include <cuda_runtime.h>
#include <cuda_bf16.h>
#include <math.h>

#define G   1000
#define NN  400
#define S   200
#define E   400
#define D   64
#define TE  399
#define NT  (G*NN)
#define OUTC 138
#define TILE 256
#define NTILES ((NT + TILE - 1) / TILE)

// ---------------- packed f32x2 helpers -------------------------------------
#define FMA2(d, a, b, c) asm("fma.rn.f32x2 %0, %1, %2, %3;" : "=l"(d) : "l"(a), "l"(b), "l"(c))
#define ADD2(d, a, b)    asm("add.rn.f32x2 %0, %1, %2;"     : "=l"(d) : "l"(a), "l"(b))
#define PACK2(out, lo, hi) asm("mov.b64 %0, {%1, %2};" : "=l"(out) : "r"(__float_as_uint(lo)), "r"(__float_as_uint(hi)))
#define UNPACK2(lo, hi, in) { unsigned _ulo, _uhi; asm("mov.b64 {%0, %1}, %2;" : "=r"(_ulo), "=r"(_uhi) : "l"(in)); lo = __uint_as_float(_ulo); hi = __uint_as_float(_uhi); }

// ---------------- scratch (device globals; no allocation allowed) ----------
__device__ int      g_cm_mode;
__device__ unsigned char g_cmm[E*S];
__device__ unsigned char g_clist[E*208];   // sparse species lists (pad w/ S)
__device__ int      g_clenpad[E];
__device__ unsigned g_cmbits[E*7];
__device__ float    g_cmsum[E];
__device__ int      g_eoff[G*401];         // edge CSR offsets (by dst)
__device__ unsigned short g_esrc[G*400];   // edge CSR srcs
__device__ int      g_noff[G*201];         // node CSR offsets (by species)
__device__ unsigned short g_nsrc[G*400];   // node CSR node ids
__device__ float    g_tv[G];               // valid species per g
__device__ float    g_nb[E*G];
__device__ float    g_avgb[E*G];
__device__ float    g_cr[E*G];
__device__ float    g_fdb[E*G];
__device__ float    g_fdo[E*G];
__device__ float    g_x[NT*D];
__device__ float    g_h[NT*D];
__device__ float    g_pool[G*S*D];
__device__ float    g_num[E*G*D];

// ---------------- helpers --------------------------------------------------
__device__ __forceinline__ float blockReduceSum256(float v, float* red) {
    int tid = threadIdx.x;
    red[tid] = v; __syncthreads();
    #pragma unroll
    for (int s = 128; s > 0; s >>= 1) {
        if (tid < s) red[tid] += red[tid + s];
        __syncthreads();
    }
    float r = red[0];
    __syncthreads();
    return r;
}

// ---------------- Kd: detect clade_mask dtype ------------------------------
__global__ void kdetect(const unsigned char* __restrict__ p) {
    __shared__ int f_mis1, f_3f1, f_3f3;
    int tid = threadIdx.x;
    if (tid == 0) { f_mis1 = 0; f_3f1 = 0; f_3f3 = 0; }
    __syncthreads();
    for (int i = tid; i < E*S; i += 256) {
        unsigned char b = p[i];
        int m = i & 3;
        if (b == 1 && m != 0)    f_mis1 = 1;
        if (b == 0x3F && m == 1) f_3f1 = 1;
        if (b == 0x3F && m == 3) f_3f3 = 1;
    }
    __syncthreads();
    if (tid == 0) {
        int mode;
        if (f_mis1)      mode = 0;
        else if (f_3f1)  mode = 3;
        else if (f_3f3)  mode = 2;
        else             mode = 1;
        g_cm_mode = mode;
    }
}

__global__ void kconvert(const void* __restrict__ p) {
    int i = blockIdx.x * 256 + threadIdx.x;
    if (i >= E*S) return;
    int mode = g_cm_mode;
    bool v;
    if      (mode == 0) v = ((const unsigned char*)p)[i] != 0;
    else if (mode == 1) v = ((const int*)p)[i] != 0;
    else if (mode == 2) v = ((const float*)p)[i] != 0.f;
    else { unsigned short u = ((const unsigned short*)p)[i]; v = (unsigned short)(u << 1) != 0; }
    g_cmm[i] = v ? 1 : 0;
}

// ---------------- K0: bitmasks + deterministic sparse lists ----------------
__global__ void k0_build() {
    int e = blockIdx.x, t = threadIdx.x;
    __shared__ int wcnt[8];
    bool bit = (t < S) && g_cmm[e*S + t];
    unsigned bal = __ballot_sync(0xffffffffu, bit);
    int w = t >> 5, lane = t & 31;
    if (lane == 0) {
        wcnt[w] = __popc(bal);
        if (w < 7) g_cmbits[e*7 + w] = bal;
    }
    __syncthreads();
    int prefix = 0;
    for (int q = 0; q < w; q++) prefix += wcnt[q];
    int pos = prefix + __popc(bal & ((1u << lane) - 1u));
    if (bit) g_clist[e*208 + pos] = (unsigned char)t;
    if (t == 0) {
        int tot = 0;
        for (int q = 0; q < 8; q++) tot += wcnt[q];
        int padded = (tot + 3) & ~3;
        for (int p2 = tot; p2 < padded; p2++) g_clist[e*208 + p2] = (unsigned char)S;
        g_clenpad[e] = padded;
        g_cmsum[e] = (float)tot;
    }
}

// ---------------- Kcsr: deterministic CSRs (O(N) match_any ranks) ----------
__global__ __launch_bounds__(512)
void kcsr(const int* __restrict__ ei, const int* __restrict__ sids) {
    int g = blockIdx.x, tid = threadIdx.x;
    __shared__ int ssrc[TE], sdst[TE], ssid[NN];
    __shared__ int cnt[NN+1], off[NN+1];
    __shared__ int cnt2[S+1], off2[S+1];
    for (int i = tid; i < TE; i += 512) { ssrc[i] = ei[g*2*TE + i]; sdst[i] = ei[g*2*TE + TE + i]; }
    for (int i = tid; i < NN; i += 512) ssid[i] = sids[g*NN + i];
    for (int i = tid; i < NN+1; i += 512) cnt[i] = 0;
    for (int i = tid; i < S+1; i += 512) cnt2[i] = 0;
    __syncthreads();
    for (int i = tid; i < TE; i += 512) atomicAdd(&cnt[sdst[i]], 1);
    for (int i = tid; i < NN; i += 512) { int sd = ssid[i]; if (sd >= 0) atomicAdd(&cnt2[sd], 1); }
    __syncthreads();
    if (tid == 0) { int a = 0; for (int n2 = 0; n2 < NN; n2++) { off[n2] = a; a += cnt[n2]; } off[NN] = a; }
    if (tid == 1) { int a = 0; for (int s = 0; s < S; s++) { off2[s] = a; a += cnt2[s]; } off2[S] = a; }
    __syncthreads();
    for (int i = tid; i <= NN; i += 512) { cnt[i] = 0; g_eoff[g*401 + i] = off[i]; }
    for (int i = tid; i <= S; i += 512)  { cnt2[i] = 0; g_noff[g*201 + i] = off2[i]; }
    __syncthreads();
    int w = tid >> 5, lane = tid & 31;
    unsigned ltm = (1u << lane) - 1u;
    if (w == 0) {
        for (int base = 0; base < TE; base += 32) {
            int i = base + lane;
            bool act = i < TE;
            int key = act ? sdst[i] : NN;
            unsigned m = __match_any_sync(0xffffffffu, key);
            int prior = cnt[key];
            __syncwarp();
            if (act) g_esrc[g*400 + off[key] + prior + __popc(m & ltm)] = (unsigned short)ssrc[i];
            if (lane == (__ffs(m) - 1)) cnt[key] = prior + __popc(m);
            __syncwarp();
        }
    } else if (w == 1) {
        for (int base = 0; base < NN; base += 32) {
            int i = base + lane;
            int sd = (i < NN) ? ssid[i] : -1;
            bool act = sd >= 0;
            int key = act ? sd : S;
            unsigned m = __match_any_sync(0xffffffffu, key);
            int prior = cnt2[key];
            __syncwarp();
            if (act) g_nsrc[g*400 + off2[key] + prior + __popc(m & ltm)] = (unsigned short)i;
            if (lane == (__ffs(m) - 1)) cnt2[key] = prior + __popc(m);
            __syncwarp();
        }
    }
}

// ---------------- K2a: per-(e,g) contrast scalars (packed f32x2 scan) ------
__global__ __launch_bounds__(256)
void k2a() {
    int g0 = blockIdx.x * 32;
    int tid = threadIdx.x, lane = tid & 31, warp = tid >> 5;
    extern __shared__ float2 pc[];                 // [32][201]
    float* tvs = (float*)(pc + 32*201);            // 3*32
    for (int idx = tid; idx < 32*201; idx += 256) {
        int gl = idx / 201, s = idx - gl*201;
        float c = 0.f;
        int g = g0 + gl;
        if (s < S && g < G) {
            int b = g_noff[g*201 + s], e2 = g_noff[g*201 + s + 1];
            c = (float)(e2 - b);
        }
        pc[gl*201 + s] = make_float2(c, ((c > 0.f) ? 1.f : 0.f) + 4096.f * ((c > 1.f) ? 1.f : 0.f));
    }
    __syncthreads();
    if (tid < 32) {
        float tv = 0.f, tc = 0.f, td = 0.f;
        for (int s = 0; s < S; s++) {
            float2 v = pc[tid*201 + s];
            tc += v.x;
            float dup = floorf(v.y * (1.f/4096.f));
            tv += v.y - 4096.f*dup;
            td += dup;
        }
        tvs[tid] = tv; tvs[32+tid] = tc; tvs[64+tid] = td;
        if (g0 + tid < G) g_tv[g0 + tid] = tv;
    }
    __syncthreads();
    int g = g0 + lane;
    bool gok = g < G;
    float tv = tvs[lane], tc = tvs[32+lane], td = tvs[64+lane];
    const float2* prow = pc + lane*201;
    for (int e = warp; e < E; e += 8) {
        const unsigned char* lp = g_clist + e*208;
        int len = g_clenpad[e];
        unsigned long long a = 0ull;
        for (int idx = 0; idx < len; idx += 4) {
            unsigned w4 = *(const unsigned*)(lp + idx);
            unsigned long long p0 = *(const unsigned long long*)&prow[w4 & 255];
            unsigned long long p1 = *(const unsigned long long*)&prow[(w4 >> 8) & 255];
            unsigned long long p2 = *(const unsigned long long*)&prow[(w4 >> 16) & 255];
            unsigned long long p3 = *(const unsigned long long*)&prow[w4 >> 24];
            ADD2(a, a, p0); ADD2(a, a, p1); ADD2(a, a, p2); ADD2(a, a, p3);
        }
        float sb, y; UNPACK2(sb, y, a);
        float db = floorf(y * (1.f/4096.f));
        float nb = y - 4096.f*db;
        float no = tv - nb, so = tc - sb, dd = td - db;
        float avgb = __fdividef(sb, fmaxf(nb, 1.f));
        float avgo = __fdividef(so, fmaxf(no, 1.f));
        float cr   = __fdividef(avgb, fmaxf(avgo, 0.1f));
        float fdb  = __fdividef(db, fmaxf(nb, 1.f));
        float fdo  = __fdividef(dd, fmaxf(no, 1.f));
        if (gok) {
            int o = e*G + g;
            g_nb[o] = nb; g_avgb[o] = avgb; g_cr[o] = cr; g_fdb[o] = fdb; g_fdo[o] = fdo;
        }
    }
}

// ---------------- K2b: per-edge masked stats -------------------------------
__global__ void k2b(float* __restrict__ out) {
    int e = blockIdx.x, tid = threadIdx.x;
    __shared__ float sA[G], sC[G], sFb[G], sFo[G], sHf[G];
    __shared__ float red[256];
    for (int g = tid; g < G; g += 256) {
        float nb = g_nb[e*G + g];
        float tv = g_tv[g];
        sA[g] = g_avgb[e*G + g]; sC[g] = g_cr[e*G + g];
        sFb[g] = g_fdb[e*G + g]; sFo[g] = g_fdo[e*G + g];
        sHf[g] = (nb > 0.f && (tv - nb) > 0.f) ? 1.f : 0.f;
    }
    __syncthreads();
    float ln = 0.f;
    for (int g = tid; g < G; g += 256) ln += sHf[g];
    float n = blockReduceSum256(ln, red);
    float cms = g_cmsum[e];
    bool okc = (cms > 0.f) && ((float)S - cms > 0.f) && (n > 0.f);
    for (int kk = 0; kk < 5; kk++) {
        float lm = 0.f;
        for (int g = tid; g < G; g += 256) {
            float v;
            if      (kk == 0) v = sA[g];
            else if (kk == 1) v = sC[g];
            else if (kk == 2) v = sFb[g];
            else if (kk == 3) v = sFo[g];
            else              v = sFb[g] - sFo[g];
            lm += v * sHf[g];
        }
        float m = blockReduceSum256(lm, red) / fmaxf(n, 1.f);
        float lv = 0.f;
        for (int g = tid; g < G; g += 256) {
            float v;
            if      (kk == 0) v = sA[g];
            else if (kk == 1) v = sC[g];
            else if (kk == 2) v = sFb[g];
            else if (kk == 3) v = sFo[g];
            else              v = sFb[g] - sFo[g];
            float dvi = v - m;
            lv += dvi * dvi * sHf[g];
        }
        float var = blockReduceSum256(lv, red) / fmaxf(n - 1.f, 1.f);
        float sv = (n > 1.f) ? sqrtf(fmaxf(var, 0.f)) : 0.f;
        if (tid == 0) {
            out[e*OUTC + 128 + 2*kk]     = okc ? m  : 0.f;
            out[e*OUTC + 128 + 2*kk + 1] = okc ? sv : 0.f;
        }
    }
}

// ---------------- K4a: GIN aggregation via edge CSR (no atomics) -----------
__global__ __launch_bounds__(512)
void k4a_agg(const int* __restrict__ sids, const float* __restrict__ emb,
             const float* __restrict__ eps, int l) {
    int g = blockIdx.x, tid = threadIdx.x;
    extern __shared__ float sm[];
    float* xs = sm;                                 // 400*64
    int* soff = (int*)(sm + NN*D);                  // 401
    unsigned short* ssrc = (unsigned short*)(soff + NN + 1);  // 400
    if (l == 0) {
        float* xg = g_x + (size_t)g * NN * D;
        for (int idx = tid; idx < NN*16; idx += 512) {
            int n2 = idx >> 4, q = idx & 15;
            int id = sids[g*NN + n2];
            if (id < 0) id = S;
            float4 v = ((const float4*)(emb + id*D))[q];
            ((float4*)xs)[idx] = v;
            ((float4*)xg)[idx] = v;
        }
    } else {
        const float* xg = g_x + (size_t)g * NN * D;
        for (int idx = tid; idx < NN*16; idx += 512)
            ((float4*)xs)[idx] = ((const float4*)xg)[idx];
    }
    for (int i = tid; i < NN+1; i += 512) soff[i] = g_eoff[g*401 + i];
    for (int i = tid; i < NN; i += 512) ssrc[i] = g_esrc[g*400 + i];
    __syncthreads();
    float e1 = 1.f + eps[l];
    int d = tid & 63;
    float* hg = g_h + (size_t)g * NN * D;
    for (int n2 = tid >> 6; n2 < NN; n2 += 8) {
        int b = soff[n2], e2 = soff[n2+1];
        float acc = 0.f;
        for (int j = b; j < e2; j++) acc += xs[(int)ssrc[j]*64 + d];
        hg[n2*64 + d] = e1 * xs[n2*64 + d] + acc;
    }
}

// ---------------- K4b: MLP + residual + LN (4x8 register-blocked f32x2) ----
// 512 threads. Thread (rg = tid>>3, pg = tid&7) owns rows rg*4..+3, cols pg*8..+7.
// smem: hs[256*68] ts[256*68] Wp1[2048]f2 Wp2[2048]f2 bp1[32]f2 bp2[32]f2 gb[128]
__global__ __launch_bounds__(512, 1)
void k4b_mlp(const float* __restrict__ W1, const float* __restrict__ b1,
             const float* __restrict__ W2, const float* __restrict__ b2,
             const float* __restrict__ gam, const float* __restrict__ bet,
             int l) {
    extern __shared__ float sm[];
    float*  hs  = sm;                       // 17408 floats
    float*  ts  = sm + 17408;               // 17408
    float2* Wp1 = (float2*)(sm + 34816);    // 2048 float2
    float2* Wp2 = (float2*)(sm + 38912);    // 2048 float2
    float2* bp1 = (float2*)(sm + 43008);    // 32 float2
    float2* bp2 = (float2*)(sm + 43072);    // 32 float2
    float*  gb  = sm + 43136;               // gamma[64], beta[64]

    int tid = threadIdx.x;
    const float* W1l = W1 + l*4096;
    const float* W2l = W2 + l*4096;
    for (int idx = tid; idx < 2048; idx += 512) {
        int j = idx >> 5, p = idx & 31;
        Wp1[idx] = make_float2(W1l[(2*p)*64 + j], W1l[(2*p+1)*64 + j]);
        Wp2[idx] = make_float2(W2l[(2*p)*64 + j], W2l[(2*p+1)*64 + j]);
    }
    if (tid < 32) {
        bp1[tid] = ((const float2*)(b1 + l*64))[tid];
        bp2[tid] = ((const float2*)(b2 + l*64))[tid];
    }
    if (tid < 64) { gb[tid] = gam[l*64 + tid]; gb[64 + tid] = bet[l*64 + tid]; }

    int pg = tid & 7, rg = tid >> 3;
    int rbase = rg * 4;
    int cbase = 8 * pg;

    for (int tile = blockIdx.x; tile < NTILES; tile += gridDim.x) {
        // ---- stage hs (also first-iteration weight sync) ----
        for (int idx = tid; idx < TILE*16; idx += 512) {
            int row = idx >> 4, q = idx & 15;
            long grow = (long)tile*TILE + row;
            float4 v = make_float4(0.f, 0.f, 0.f, 0.f);
            if (grow < NT) v = *(const float4*)(g_h + grow*64 + q*4);
            *(float4*)&hs[row*68 + q*4] = v;
        }
        __syncthreads();

        // ---- GEMM1: t = relu(h @ W1^T + b1) ----
        unsigned long long acc[16];
        #pragma unroll
        for (int pp = 0; pp < 4; pp++) {
            float2 b = bp1[pg*4 + pp];
            unsigned long long bb; PACK2(bb, b.x, b.y);
            #pragma unroll
            for (int rr = 0; rr < 4; rr++) acc[rr*4 + pp] = bb;
        }
        #pragma unroll 1
        for (int jb = 0; jb < 16; jb++) {
            float4 h4[4];
            #pragma unroll
            for (int rr = 0; rr < 4; rr++)
                h4[rr] = *(const float4*)&hs[(rbase + rr)*68 + jb*4];
            #pragma unroll
            for (int jj = 0; jj < 4; jj++) {
                unsigned long long w2[4];
                #pragma unroll
                for (int pp = 0; pp < 4; pp++)
                    w2[pp] = *(const unsigned long long*)&Wp1[(jb*4 + jj)*32 + pg*4 + pp];
                unsigned long long hd[4];
                #pragma unroll
                for (int rr = 0; rr < 4; rr++) {
                    float hv = (jj == 0) ? h4[rr].x : (jj == 1) ? h4[rr].y : (jj == 2) ? h4[rr].z : h4[rr].w;
                    PACK2(hd[rr], hv, hv);
                }
                #pragma unroll
                for (int rr = 0; rr < 4; rr++)
                    #pragma unroll
                    for (int pp = 0; pp < 4; pp++)
                        FMA2(acc[rr*4 + pp], hd[rr], w2[pp], acc[rr*4 + pp]);
            }
        }
        // relu -> ts
        #pragma unroll
        for (int rr = 0; rr < 4; rr++)
            #pragma unroll
            for (int pp = 0; pp < 4; pp++) {
                float lo, hi; UNPACK2(lo, hi, acc[rr*4 + pp]);
                lo = fmaxf(lo, 0.f); hi = fmaxf(hi, 0.f);
                unsigned long long t2; PACK2(t2, lo, hi);
                *(unsigned long long*)&ts[(rbase + rr)*68 + cbase + 2*pp] = t2;
            }
        __syncthreads();

        // ---- GEMM2: y = t @ W2^T + b2 ----
        #pragma unroll
        for (int pp = 0; pp < 4; pp++) {
            float2 b = bp2[pg*4 + pp];
            unsigned long long bb; PACK2(bb, b.x, b.y);
            #pragma unroll
            for (int rr = 0; rr < 4; rr++) acc[rr*4 + pp] = bb;
        }
        #pragma unroll 1
        for (int jb = 0; jb < 16; jb++) {
            float4 h4[4];
            #pragma unroll
            for (int rr = 0; rr < 4; rr++)
                h4[rr] = *(const float4*)&ts[(rbase + rr)*68 + jb*4];
            #pragma unroll
            for (int jj = 0; jj < 4; jj++) {
                unsigned long long w2[4];
                #pragma unroll
                for (int pp = 0; pp < 4; pp++)
                    w2[pp] = *(const unsigned long long*)&Wp2[(jb*4 + jj)*32 + pg*4 + pp];
                unsigned long long hd[4];
                #pragma unroll
                for (int rr = 0; rr < 4; rr++) {
                    float hv = (jj == 0) ? h4[rr].x : (jj == 1) ? h4[rr].y : (jj == 2) ? h4[rr].z : h4[rr].w;
                    PACK2(hd[rr], hv, hv);
                }
                #pragma unroll
                for (int rr = 0; rr < 4; rr++)
                    #pragma unroll
                    for (int pp = 0; pp < 4; pp++)
                        FMA2(acc[rr*4 + pp], hd[rr], w2[pp], acc[rr*4 + pp]);
            }
        }

        // ---- residual + LayerNorm ----
        #pragma unroll
        for (int rr = 0; rr < 4; rr++) {
            long grow = (long)tile*TILE + rbase + rr;
            bool ok = grow < NT;
            float lo[4], hi[4];
            #pragma unroll
            for (int pp = 0; pp < 4; pp++) {
                UNPACK2(lo[pp], hi[pp], acc[rr*4 + pp]);
                if (ok) {
                    float2 xv = *(const float2*)(g_x + grow*64 + cbase + 2*pp);
                    lo[pp] += xv.x; hi[pp] += xv.y;
                }
            }
            float s = 0.f;
            #pragma unroll
            for (int pp = 0; pp < 4; pp++) s += lo[pp] + hi[pp];
            s += __shfl_xor_sync(0xffffffffu, s, 1);
            s += __shfl_xor_sync(0xffffffffu, s, 2);
            s += __shfl_xor_sync(0xffffffffu, s, 4);
            float mu = s * (1.f/64.f);
            float vs = 0.f;
            #pragma unroll
            for (int pp = 0; pp < 4; pp++) {
                float a2 = lo[pp] - mu, b2 = hi[pp] - mu;
                vs += a2*a2 + b2*b2;
            }
            vs += __shfl_xor_sync(0xffffffffu, vs, 1);
            vs += __shfl_xor_sync(0xffffffffu, vs, 2);
            vs += __shfl_xor_sync(0xffffffffu, vs, 4);
            float rs = rsqrtf(vs * (1.f/64.f) + 1e-5f);
            if (ok) {
                #pragma unroll
                for (int pp = 0; pp < 4; pp++) {
                    float2 gg = *(const float2*)&gb[cbase + 2*pp];
                    float2 bb2 = *(const float2*)&gb[64 + cbase + 2*pp];
                    float2 o;
                    o.x = (lo[pp] - mu) * rs * gg.x + bb2.x;
                    o.y = (hi[pp] - mu) * rs * gg.y + bb2.y;
                    *(float2*)(g_x + grow*64 + cbase + 2*pp) = o;
                }
            }
        }
        __syncthreads();
    }
}

// ---------------- K5: per-(g,s) mean pooling via node CSR ------------------
__global__ __launch_bounds__(256)
void k5_pool() {
    int g = blockIdx.x, tid = threadIdx.x;
    __shared__ int soff[S+1];
    __shared__ unsigned short snod[NN];
    for (int i = tid; i < S+1; i += 256) soff[i] = g_noff[g*201 + i];
    for (int i = tid; i < NN; i += 256) snod[i] = g_nsrc[g*400 + i];
    __syncthreads();
    const float* xg = g_x + (size_t)g * NN * D;
    float* pg = g_pool + (size_t)g * S * D;
    int d = tid & 63;
    for (int s = tid >> 6; s < S; s += 4) {
        int b = soff[s], e2 = soff[s+1];
        float acc = 0.f;
        for (int j = b; j < e2; j++) acc += xg[(int)snod[j]*64 + d];
        int c = e2 - b;
        pg[s*64 + d] = (c > 0) ? acc / (float)c : 0.f;
    }
}

// ---------------- K6: gt_means via sparse lists + f32x2 --------------------
__global__ __launch_bounds__(256)
void k6_num() {
    int g = blockIdx.x;
    extern __shared__ float Ps[];               // 201*64
    int tid = threadIdx.x;
    const float* pg = g_pool + (size_t)g * S * D;
    for (int idx = tid; idx < 3200; idx += 256)
        ((float4*)Ps)[idx] = ((const float4*)pg)[idx];
    if (tid < 64) Ps[S*64 + tid] = 0.f;
    __syncthreads();

    int w = tid >> 5, ii = tid & 31;
    for (int e = w*50; e < w*50 + 50; e++) {
        const unsigned char* lp = g_clist + e*208;
        int len = g_clenpad[e];
        unsigned long long a0 = 0ull, a1 = 0ull;
        for (int idx = 0; idx < len; idx += 4) {
            unsigned w4 = *(const unsigned*)(lp + idx);
            int s0 =  w4        & 255;
            int s1 = (w4 >> 8)  & 255;
            int s2 = (w4 >> 16) & 255;
            int s3 =  w4 >> 24;
            unsigned long long p0 = *(const unsigned long long*)&Ps[s0*64 + 2*ii];
            unsigned long long p1 = *(const unsigned long long*)&Ps[s1*64 + 2*ii];
            unsigned long long p2 = *(const unsigned long long*)&Ps[s2*64 + 2*ii];
            unsigned long long p3 = *(const unsigned long long*)&Ps[s3*64 + 2*ii];
            ADD2(a0, a0, p0);
            ADD2(a1, a1, p1);
            ADD2(a0, a0, p2);
            ADD2(a1, a1, p3);
        }
        ADD2(a0, a0, a1);
        float lo, hi; UNPACK2(lo, hi, a0);
        float nb = g_nb[e*G + g];
        float inv = 1.f / fmaxf(nb, 1.f);
        float2 o; o.x = lo * inv; o.y = hi * inv;
        *(float2*)&g_num[((size_t)e*G + g)*64 + 2*ii] = o;
    }
}

// ---------------- K7: per-edge mean/std of gt_means ------------------------
__global__ void k7_feats(float* __restrict__ out) {
    int e = blockIdx.x, tid = threadIdx.x;
    int part = tid >> 6, d = tid & 63;
    __shared__ float sp[4][64];
    __shared__ float smean[64];
    __shared__ float red[256];

    float ln = 0.f;
    for (int g = tid; g < G; g += 256) ln += (g_nb[e*G + g] > 0.f) ? 1.f : 0.f;
    float n2 = blockReduceSum256(ln, red);

    float acc = 0.f;
    for (int g = part; g < G; g += 4) {
        if (g_nb[e*G + g] > 0.f)
            acc += g_num[((size_t)e*G + g)*64 + d];
    }
    sp[part][d] = acc;
    __syncthreads();
    if (tid < 64)
        smean[tid] = (sp[0][tid] + sp[1][tid] + sp[2][tid] + sp[3][tid]) / fmaxf(n2, 1.f);
    __syncthreads();
    float m = smean[d];

    float acc2 = 0.f;
    for (int g = part; g < G; g += 4) {
        if (g_nb[e*G + g] > 0.f) {
            float v = g_num[((size_t)e*G + g)*64 + d] - m;
            acc2 += v * v;
        }
    }
    sp[part][d] = acc2;
    __syncthreads();
    if (tid < 64) {
        float var = (sp[0][tid] + sp[1][tid] + sp[2][tid] + sp[3][tid]) / fmaxf(n2 - 1.f, 1.f);
        float sv = (n2 > 1.f) ? sqrtf(fmaxf(var, 0.f)) : 0.f;
        bool ok = (g_cmsum[e] > 0.f) && (n2 > 0.f);
        out[e*OUTC + tid]      = ok ? smean[tid] : 0.f;
        out[e*OUTC + 64 + tid] = ok ? sv : 0.f;
    }
}

// ---------------- launch ---------------------------------------------------
extern "C" void kernel_launch(void* const* d_in, const int* in_sizes, int n_in,
                              void* d_out, int out_size) {
    const int*   sids = (const int*)d_in[0];
    const void*  cmraw = d_in[3];
    const int*   ei   = (const int*)d_in[2];
    const float* emb  = (const float*)d_in[4];
    const float* W1   = (const float*)d_in[5];
    const float* b1   = (const float*)d_in[6];
    const float* W2   = (const float*)d_in[7];
    const float* b2   = (const float*)d_in[8];
    const float* eps  = (const float*)d_in[9];
    const float* gam  = (const float*)d_in[10];
    const float* bet  = (const float*)d_in[11];
    float* out = (float*)d_out;

    const int SM_K4A = NN*D*4 + (NN+1)*4 + NN*2;   // 104804
    const int SM_K4B = 43264 * 4;                  // 173056
    const int SM_K2A = 32*201*8 + 96*4;            // 51840
    const int SM_K6  = (S+1)*D*4;                  // 51456
    cudaFuncSetAttribute(k4a_agg, cudaFuncAttributeMaxDynamicSharedMemorySize, SM_K4A);
    cudaFuncSetAttribute(k4b_mlp, cudaFuncAttributeMaxDynamicSharedMemorySize, SM_K4B);
    cudaFuncSetAttribute(k2a,     cudaFuncAttributeMaxDynamicSharedMemorySize, SM_K2A);
    cudaFuncSetAttribute(k6_num,  cudaFuncAttributeMaxDynamicSharedMemorySize, SM_K6);

    // Order keeps k4b_mlp at profiler launch slot #4.
    kcsr<<<G, 512>>>(ei, sids);                                    // 1
    k4a_agg<<<G, 512, SM_K4A>>>(sids, emb, eps, 0);                // 2
    kdetect<<<1, 256>>>((const unsigned char*)cmraw);              // 3
    k4b_mlp<<<148, 512, SM_K4B>>>(W1, b1, W2, b2, gam, bet, 0);    // 4  <- profiled
    kconvert<<<(E*S + 255)/256, 256>>>(cmraw);                     // 5
    k0_build<<<E, 256>>>();                                        // 6
    k4a_agg<<<G, 512, SM_K4A>>>(sids, emb, eps, 1);                // 7
    k4b_mlp<<<148, 512, SM_K4B>>>(W1, b1, W2, b2, gam, bet, 1);    // 8
    k2a<<<(G + 31)/32, 256, SM_K2A>>>();                           // 9
    k2b<<<E, 256>>>(out);                                          // 10
    k5_pool<<<G, 256>>>();                                         // 11
    k6_num<<<G, 256, SM_K6>>>();                                   // 12
    k7_feats<<<E, 256>>>(out);                                     // 13
}

// round 12
// speedup vs baseline: 1.1001x; 1.1001x over previous
#include <cuda_runtime.h>
#include <cuda_bf16.h>
#include <cstdint>
#include <math.h>

#define G   1000
#define NN  400
#define S   200
#define E   400
#define D   64
#define TE  399
#define NT  (G*NN)
#define OUTC 138
#define TILE 256
#define NTILES ((NT + TILE - 1) / TILE)

// ---------------- packed f32x2 helpers -------------------------------------
#define FMA2(d, a, b, c) asm("fma.rn.f32x2 %0, %1, %2, %3;" : "=l"(d) : "l"(a), "l"(b), "l"(c))
#define ADD2(d, a, b)    asm("add.rn.f32x2 %0, %1, %2;"     : "=l"(d) : "l"(a), "l"(b))
#define PACK2(out, lo, hi) asm("mov.b64 %0, {%1, %2};" : "=l"(out) : "r"(__float_as_uint(lo)), "r"(__float_as_uint(hi)))
#define UNPACK2(lo, hi, in) { unsigned _ulo, _uhi; asm("mov.b64 {%0, %1}, %2;" : "=r"(_ulo), "=r"(_uhi) : "l"(in)); lo = __uint_as_float(_ulo); hi = __uint_as_float(_uhi); }

// ---------------- scratch (device globals; no allocation allowed) ----------
__device__ int      g_cm_mode;
__device__ unsigned char g_cmm[E*S];
__device__ unsigned char g_clist[E*208];   // sparse species lists (pad w/ S)
__device__ int      g_clenpad[E];
__device__ unsigned g_cmbits[E*7];
__device__ float    g_cmsum[E];
__device__ int      g_eoff[G*401];         // edge CSR offsets (by dst)
__device__ unsigned short g_esrc[G*400];   // edge CSR srcs
__device__ int      g_noff[G*201];         // node CSR offsets (by species)
__device__ unsigned short g_nsrc[G*400];   // node CSR node ids
__device__ float    g_tv[G];               // valid species per g
__device__ float    g_nb[E*G];
__device__ float    g_avgb[E*G];
__device__ float    g_cr[E*G];
__device__ float    g_fdb[E*G];
__device__ float    g_fdo[E*G];
__device__ float    g_x[NT*D];
__device__ float    g_h[NT*D];
__device__ float    g_pool[G*S*D];
__device__ float    g_num[E*G*D];

// ---------------- helpers --------------------------------------------------
__device__ __forceinline__ float blockReduceSum256(float v, float* red) {
    int tid = threadIdx.x;
    red[tid] = v; __syncthreads();
    #pragma unroll
    for (int s = 128; s > 0; s >>= 1) {
        if (tid < s) red[tid] += red[tid + s];
        __syncthreads();
    }
    float r = red[0];
    __syncthreads();
    return r;
}

// ---------------- Kd: detect clade_mask dtype ------------------------------
__global__ void kdetect(const unsigned char* __restrict__ p) {
    __shared__ int f_mis1, f_3f1, f_3f3;
    int tid = threadIdx.x;
    if (tid == 0) { f_mis1 = 0; f_3f1 = 0; f_3f3 = 0; }
    __syncthreads();
    for (int i = tid; i < E*S; i += 256) {
        unsigned char b = p[i];
        int m = i & 3;
        if (b == 1 && m != 0)    f_mis1 = 1;
        if (b == 0x3F && m == 1) f_3f1 = 1;
        if (b == 0x3F && m == 3) f_3f3 = 1;
    }
    __syncthreads();
    if (tid == 0) {
        int mode;
        if (f_mis1)      mode = 0;
        else if (f_3f1)  mode = 3;
        else if (f_3f3)  mode = 2;
        else             mode = 1;
        g_cm_mode = mode;
    }
}

__global__ void kconvert(const void* __restrict__ p) {
    int i = blockIdx.x * 256 + threadIdx.x;
    if (i >= E*S) return;
    int mode = g_cm_mode;
    bool v;
    if      (mode == 0) v = ((const unsigned char*)p)[i] != 0;
    else if (mode == 1) v = ((const int*)p)[i] != 0;
    else if (mode == 2) v = ((const float*)p)[i] != 0.f;
    else { unsigned short u = ((const unsigned short*)p)[i]; v = (unsigned short)(u << 1) != 0; }
    g_cmm[i] = v ? 1 : 0;
}

// ---------------- K0: bitmasks + deterministic sparse lists ----------------
__global__ void k0_build() {
    int e = blockIdx.x, t = threadIdx.x;
    __shared__ int wcnt[8];
    bool bit = (t < S) && g_cmm[e*S + t];
    unsigned bal = __ballot_sync(0xffffffffu, bit);
    int w = t >> 5, lane = t & 31;
    if (lane == 0) {
        wcnt[w] = __popc(bal);
        if (w < 7) g_cmbits[e*7 + w] = bal;
    }
    __syncthreads();
    int prefix = 0;
    for (int q = 0; q < w; q++) prefix += wcnt[q];
    int pos = prefix + __popc(bal & ((1u << lane) - 1u));
    if (bit) g_clist[e*208 + pos] = (unsigned char)t;
    if (t == 0) {
        int tot = 0;
        for (int q = 0; q < 8; q++) tot += wcnt[q];
        int padded = (tot + 3) & ~3;
        for (int p2 = tot; p2 < padded; p2++) g_clist[e*208 + p2] = (unsigned char)S;
        g_clenpad[e] = padded;
        g_cmsum[e] = (float)tot;
    }
}

// ---------------- Kcsr: deterministic CSRs (O(N) match_any ranks) ----------
__global__ __launch_bounds__(512)
void kcsr(const int* __restrict__ ei, const int* __restrict__ sids) {
    int g = blockIdx.x, tid = threadIdx.x;
    __shared__ int ssrc[TE], sdst[TE], ssid[NN];
    __shared__ int cnt[NN+1], off[NN+1];
    __shared__ int cnt2[S+1], off2[S+1];
    for (int i = tid; i < TE; i += 512) { ssrc[i] = ei[g*2*TE + i]; sdst[i] = ei[g*2*TE + TE + i]; }
    for (int i = tid; i < NN; i += 512) ssid[i] = sids[g*NN + i];
    for (int i = tid; i < NN+1; i += 512) cnt[i] = 0;
    for (int i = tid; i < S+1; i += 512) cnt2[i] = 0;
    __syncthreads();
    for (int i = tid; i < TE; i += 512) atomicAdd(&cnt[sdst[i]], 1);
    for (int i = tid; i < NN; i += 512) { int sd = ssid[i]; if (sd >= 0) atomicAdd(&cnt2[sd], 1); }
    __syncthreads();
    if (tid == 0) { int a = 0; for (int n2 = 0; n2 < NN; n2++) { off[n2] = a; a += cnt[n2]; } off[NN] = a; }
    if (tid == 1) { int a = 0; for (int s = 0; s < S; s++) { off2[s] = a; a += cnt2[s]; } off2[S] = a; }
    __syncthreads();
    for (int i = tid; i <= NN; i += 512) { cnt[i] = 0; g_eoff[g*401 + i] = off[i]; }
    for (int i = tid; i <= S; i += 512)  { cnt2[i] = 0; g_noff[g*201 + i] = off2[i]; }
    __syncthreads();
    int w = tid >> 5, lane = tid & 31;
    unsigned ltm = (1u << lane) - 1u;
    if (w == 0) {
        for (int base = 0; base < TE; base += 32) {
            int i = base + lane;
            bool act = i < TE;
            int key = act ? sdst[i] : NN;
            unsigned m = __match_any_sync(0xffffffffu, key);
            int prior = cnt[key];
            __syncwarp();
            if (act) g_esrc[g*400 + off[key] + prior + __popc(m & ltm)] = (unsigned short)ssrc[i];
            if (lane == (__ffs(m) - 1)) cnt[key] = prior + __popc(m);
            __syncwarp();
        }
    } else if (w == 1) {
        for (int base = 0; base < NN; base += 32) {
            int i = base + lane;
            int sd = (i < NN) ? ssid[i] : -1;
            bool act = sd >= 0;
            int key = act ? sd : S;
            unsigned m = __match_any_sync(0xffffffffu, key);
            int prior = cnt2[key];
            __syncwarp();
            if (act) g_nsrc[g*400 + off2[key] + prior + __popc(m & ltm)] = (unsigned short)i;
            if (lane == (__ffs(m) - 1)) cnt2[key] = prior + __popc(m);
            __syncwarp();
        }
    }
}

// ---------------- K2a: per-(e,g) contrast scalars (packed f32x2 scan) ------
__global__ __launch_bounds__(256)
void k2a() {
    int g0 = blockIdx.x * 32;
    int tid = threadIdx.x, lane = tid & 31, warp = tid >> 5;
    extern __shared__ float2 pc[];                 // [32][201]
    float* tvs = (float*)(pc + 32*201);
    for (int idx = tid; idx < 32*201; idx += 256) {
        int gl = idx / 201, s = idx - gl*201;
        float c = 0.f;
        int g = g0 + gl;
        if (s < S && g < G) {
            int b = g_noff[g*201 + s], e2 = g_noff[g*201 + s + 1];
            c = (float)(e2 - b);
        }
        pc[gl*201 + s] = make_float2(c, ((c > 0.f) ? 1.f : 0.f) + 4096.f * ((c > 1.f) ? 1.f : 0.f));
    }
    __syncthreads();
    if (tid < 32) {
        float tv = 0.f, tc = 0.f, td = 0.f;
        for (int s = 0; s < S; s++) {
            float2 v = pc[tid*201 + s];
            tc += v.x;
            float dup = floorf(v.y * (1.f/4096.f));
            tv += v.y - 4096.f*dup;
            td += dup;
        }
        tvs[tid] = tv; tvs[32+tid] = tc; tvs[64+tid] = td;
        if (g0 + tid < G) g_tv[g0 + tid] = tv;
    }
    __syncthreads();
    int g = g0 + lane;
    bool gok = g < G;
    float tv = tvs[lane], tc = tvs[32+lane], td = tvs[64+lane];
    const float2* prow = pc + lane*201;
    for (int e = warp; e < E; e += 8) {
        const unsigned char* lp = g_clist + e*208;
        int len = g_clenpad[e];
        unsigned long long a = 0ull;
        for (int idx = 0; idx < len; idx += 4) {
            unsigned w4 = *(const unsigned*)(lp + idx);
            unsigned long long p0 = *(const unsigned long long*)&prow[w4 & 255];
            unsigned long long p1 = *(const unsigned long long*)&prow[(w4 >> 8) & 255];
            unsigned long long p2 = *(const unsigned long long*)&prow[(w4 >> 16) & 255];
            unsigned long long p3 = *(const unsigned long long*)&prow[w4 >> 24];
            ADD2(a, a, p0); ADD2(a, a, p1); ADD2(a, a, p2); ADD2(a, a, p3);
        }
        float sb, y; UNPACK2(sb, y, a);
        float db = floorf(y * (1.f/4096.f));
        float nb = y - 4096.f*db;
        float no = tv - nb, so = tc - sb, dd = td - db;
        float avgb = __fdividef(sb, fmaxf(nb, 1.f));
        float avgo = __fdividef(so, fmaxf(no, 1.f));
        float cr   = __fdividef(avgb, fmaxf(avgo, 0.1f));
        float fdb  = __fdividef(db, fmaxf(nb, 1.f));
        float fdo  = __fdividef(dd, fmaxf(no, 1.f));
        if (gok) {
            int o = e*G + g;
            g_nb[o] = nb; g_avgb[o] = avgb; g_cr[o] = cr; g_fdb[o] = fdb; g_fdo[o] = fdo;
        }
    }
}

// ---------------- K2b: per-edge masked stats -------------------------------
__global__ void k2b(float* __restrict__ out) {
    int e = blockIdx.x, tid = threadIdx.x;
    __shared__ float sA[G], sC[G], sFb[G], sFo[G], sHf[G];
    __shared__ float red[256];
    for (int g = tid; g < G; g += 256) {
        float nb = g_nb[e*G + g];
        float tv = g_tv[g];
        sA[g] = g_avgb[e*G + g]; sC[g] = g_cr[e*G + g];
        sFb[g] = g_fdb[e*G + g]; sFo[g] = g_fdo[e*G + g];
        sHf[g] = (nb > 0.f && (tv - nb) > 0.f) ? 1.f : 0.f;
    }
    __syncthreads();
    float ln = 0.f;
    for (int g = tid; g < G; g += 256) ln += sHf[g];
    float n = blockReduceSum256(ln, red);
    float cms = g_cmsum[e];
    bool okc = (cms > 0.f) && ((float)S - cms > 0.f) && (n > 0.f);
    for (int kk = 0; kk < 5; kk++) {
        float lm = 0.f;
        for (int g = tid; g < G; g += 256) {
            float v;
            if      (kk == 0) v = sA[g];
            else if (kk == 1) v = sC[g];
            else if (kk == 2) v = sFb[g];
            else if (kk == 3) v = sFo[g];
            else              v = sFb[g] - sFo[g];
            lm += v * sHf[g];
        }
        float m = blockReduceSum256(lm, red) / fmaxf(n, 1.f);
        float lv = 0.f;
        for (int g = tid; g < G; g += 256) {
            float v;
            if      (kk == 0) v = sA[g];
            else if (kk == 1) v = sC[g];
            else if (kk == 2) v = sFb[g];
            else if (kk == 3) v = sFo[g];
            else              v = sFb[g] - sFo[g];
            float dvi = v - m;
            lv += dvi * dvi * sHf[g];
        }
        float var = blockReduceSum256(lv, red) / fmaxf(n - 1.f, 1.f);
        float sv = (n > 1.f) ? sqrtf(fmaxf(var, 0.f)) : 0.f;
        if (tid == 0) {
            out[e*OUTC + 128 + 2*kk]     = okc ? m  : 0.f;
            out[e*OUTC + 128 + 2*kk + 1] = okc ? sv : 0.f;
        }
    }
}

// ---------------- K4a: GIN aggregation via edge CSR (no atomics) -----------
__global__ __launch_bounds__(512)
void k4a_agg(const int* __restrict__ sids, const float* __restrict__ emb,
             const float* __restrict__ eps, int l) {
    int g = blockIdx.x, tid = threadIdx.x;
    extern __shared__ float sm[];
    float* xs = sm;
    int* soff = (int*)(sm + NN*D);
    unsigned short* ssrc = (unsigned short*)(soff + NN + 1);
    if (l == 0) {
        float* xg = g_x + (size_t)g * NN * D;
        for (int idx = tid; idx < NN*16; idx += 512) {
            int n2 = idx >> 4, q = idx & 15;
            int id = sids[g*NN + n2];
            if (id < 0) id = S;
            float4 v = ((const float4*)(emb + id*D))[q];
            ((float4*)xs)[idx] = v;
            ((float4*)xg)[idx] = v;
        }
    } else {
        const float* xg = g_x + (size_t)g * NN * D;
        for (int idx = tid; idx < NN*16; idx += 512)
            ((float4*)xs)[idx] = ((const float4*)xg)[idx];
    }
    for (int i = tid; i < NN+1; i += 512) soff[i] = g_eoff[g*401 + i];
    for (int i = tid; i < NN; i += 512) ssrc[i] = g_esrc[g*400 + i];
    __syncthreads();
    float e1 = 1.f + eps[l];
    int d = tid & 63;
    float* hg = g_h + (size_t)g * NN * D;
    for (int n2 = tid >> 6; n2 < NN; n2 += 8) {
        int b = soff[n2], e2 = soff[n2+1];
        float acc = 0.f;
        for (int j = b; j < e2; j++) acc += xs[(int)ssrc[j]*64 + d];
        hg[n2*64 + d] = e1 * xs[n2*64 + d] + acc;
    }
}

// ---------------- K4b: MLP + residual + LN (8x8 blocked, interleaved rows) -
// Thread (rg = tid>>3, pg = tid&7) owns rows {rg + 32*rr : rr=0..7}, cols pg*8..+7.
// Interleaved rows: per-rr warp LDS addresses differ by rg*68 -> rg*4 banks
// (conflict-free, 8-lane broadcast). LN over 8 consecutive lanes unchanged.
// smem: hs[256*68] ts[256*68] Wp1[2048]f2 Wp2[2048]f2 bp1[32]f2 bp2[32]f2 gb[128]
__global__ __launch_bounds__(256, 1)
void k4b_mlp(const float* __restrict__ W1, const float* __restrict__ b1,
             const float* __restrict__ W2, const float* __restrict__ b2,
             const float* __restrict__ gam, const float* __restrict__ bet,
             int l) {
    extern __shared__ float sm[];
    float*  hs  = sm;                       // 17408 floats
    float*  ts  = sm + 17408;               // 17408
    float2* Wp1 = (float2*)(sm + 34816);    // 2048 float2
    float2* Wp2 = (float2*)(sm + 38912);    // 2048 float2
    float2* bp1 = (float2*)(sm + 43008);    // 32 float2
    float2* bp2 = (float2*)(sm + 43072);    // 32 float2
    float*  gb  = sm + 43136;               // gamma[64], beta[64]

    int tid = threadIdx.x;
    const float* W1l = W1 + l*4096;
    const float* W2l = W2 + l*4096;
    for (int idx = tid; idx < 2048; idx += 256) {
        int j = idx >> 5, p = idx & 31;
        Wp1[idx] = make_float2(W1l[(2*p)*64 + j], W1l[(2*p+1)*64 + j]);
        Wp2[idx] = make_float2(W2l[(2*p)*64 + j], W2l[(2*p+1)*64 + j]);
    }
    if (tid < 32) {
        bp1[tid] = ((const float2*)(b1 + l*64))[tid];
        bp2[tid] = ((const float2*)(b2 + l*64))[tid];
    }
    if (tid < 64) { gb[tid] = gam[l*64 + tid]; gb[64 + tid] = bet[l*64 + tid]; }

    int pg = tid & 7, rg = tid >> 3;        // rg: 0..31
    int cbase = 8 * pg;

    for (int tile = blockIdx.x; tile < NTILES; tile += gridDim.x) {
        // ---- stage hs (also first-iteration weight sync) ----
        for (int idx = tid; idx < TILE*16; idx += 256) {
            int row = idx >> 4, q = idx & 15;
            long grow = (long)tile*TILE + row;
            float4 v = make_float4(0.f, 0.f, 0.f, 0.f);
            if (grow < NT) v = *(const float4*)(g_h + grow*64 + q*4);
            *(float4*)&hs[row*68 + q*4] = v;
        }
        __syncthreads();

        // ---- GEMM1: t = relu(h @ W1^T + b1) ----
        unsigned long long acc[32];
        #pragma unroll
        for (int pp = 0; pp < 4; pp++) {
            float2 b = bp1[pg*4 + pp];
            unsigned long long bb; PACK2(bb, b.x, b.y);
            #pragma unroll
            for (int rr = 0; rr < 8; rr++) acc[rr*4 + pp] = bb;
        }
        #pragma unroll 1
        for (int jb = 0; jb < 16; jb++) {
            float4 h4[8];
            #pragma unroll
            for (int rr = 0; rr < 8; rr++)
                h4[rr] = *(const float4*)&hs[(rg + 32*rr)*68 + jb*4];
            #pragma unroll
            for (int jj = 0; jj < 4; jj++) {
                unsigned long long w2[4];
                #pragma unroll
                for (int pp = 0; pp < 4; pp++)
                    w2[pp] = *(const unsigned long long*)&Wp1[(jb*4 + jj)*32 + pg*4 + pp];
                unsigned long long hd[8];
                #pragma unroll
                for (int rr = 0; rr < 8; rr++) {
                    float hv = (jj == 0) ? h4[rr].x : (jj == 1) ? h4[rr].y : (jj == 2) ? h4[rr].z : h4[rr].w;
                    PACK2(hd[rr], hv, hv);
                }
                #pragma unroll
                for (int rr = 0; rr < 8; rr++)
                    #pragma unroll
                    for (int pp = 0; pp < 4; pp++)
                        FMA2(acc[rr*4 + pp], hd[rr], w2[pp], acc[rr*4 + pp]);
            }
        }
        // relu -> ts
        #pragma unroll
        for (int rr = 0; rr < 8; rr++)
            #pragma unroll
            for (int pp = 0; pp < 4; pp++) {
                float lo, hi; UNPACK2(lo, hi, acc[rr*4 + pp]);
                lo = fmaxf(lo, 0.f); hi = fmaxf(hi, 0.f);
                unsigned long long t2; PACK2(t2, lo, hi);
                *(unsigned long long*)&ts[(rg + 32*rr)*68 + cbase + 2*pp] = t2;
            }
        __syncthreads();

        // ---- GEMM2: y = t @ W2^T + b2 ----
        #pragma unroll
        for (int pp = 0; pp < 4; pp++) {
            float2 b = bp2[pg*4 + pp];
            unsigned long long bb; PACK2(bb, b.x, b.y);
            #pragma unroll
            for (int rr = 0; rr < 8; rr++) acc[rr*4 + pp] = bb;
        }
        #pragma unroll 1
        for (int jb = 0; jb < 16; jb++) {
            float4 h4[8];
            #pragma unroll
            for (int rr = 0; rr < 8; rr++)
                h4[rr] = *(const float4*)&ts[(rg + 32*rr)*68 + jb*4];
            #pragma unroll
            for (int jj = 0; jj < 4; jj++) {
                unsigned long long w2[4];
                #pragma unroll
                for (int pp = 0; pp < 4; pp++)
                    w2[pp] = *(const unsigned long long*)&Wp2[(jb*4 + jj)*32 + pg*4 + pp];
                unsigned long long hd[8];
                #pragma unroll
                for (int rr = 0; rr < 8; rr++) {
                    float hv = (jj == 0) ? h4[rr].x : (jj == 1) ? h4[rr].y : (jj == 2) ? h4[rr].z : h4[rr].w;
                    PACK2(hd[rr], hv, hv);
                }
                #pragma unroll
                for (int rr = 0; rr < 8; rr++)
                    #pragma unroll
                    for (int pp = 0; pp < 4; pp++)
                        FMA2(acc[rr*4 + pp], hd[rr], w2[pp], acc[rr*4 + pp]);
            }
        }

        // ---- residual + LayerNorm ----
        #pragma unroll
        for (int rr = 0; rr < 8; rr++) {
            long grow = (long)tile*TILE + rg + 32*rr;
            bool ok = grow < NT;
            float lo[4], hi[4];
            #pragma unroll
            for (int pp = 0; pp < 4; pp++) {
                UNPACK2(lo[pp], hi[pp], acc[rr*4 + pp]);
                if (ok) {
                    float2 xv = *(const float2*)(g_x + grow*64 + cbase + 2*pp);
                    lo[pp] += xv.x; hi[pp] += xv.y;
                }
            }
            float s = 0.f;
            #pragma unroll
            for (int pp = 0; pp < 4; pp++) s += lo[pp] + hi[pp];
            s += __shfl_xor_sync(0xffffffffu, s, 1);
            s += __shfl_xor_sync(0xffffffffu, s, 2);
            s += __shfl_xor_sync(0xffffffffu, s, 4);
            float mu = s * (1.f/64.f);
            float vs = 0.f;
            #pragma unroll
            for (int pp = 0; pp < 4; pp++) {
                float a2 = lo[pp] - mu, b2 = hi[pp] - mu;
                vs += a2*a2 + b2*b2;
            }
            vs += __shfl_xor_sync(0xffffffffu, vs, 1);
            vs += __shfl_xor_sync(0xffffffffu, vs, 2);
            vs += __shfl_xor_sync(0xffffffffu, vs, 4);
            float rs = rsqrtf(vs * (1.f/64.f) + 1e-5f);
            if (ok) {
                #pragma unroll
                for (int pp = 0; pp < 4; pp++) {
                    float2 gg = *(const float2*)&gb[cbase + 2*pp];
                    float2 bb2 = *(const float2*)&gb[64 + cbase + 2*pp];
                    float2 o;
                    o.x = (lo[pp] - mu) * rs * gg.x + bb2.x;
                    o.y = (hi[pp] - mu) * rs * gg.y + bb2.y;
                    *(float2*)(g_x + grow*64 + cbase + 2*pp) = o;
                }
            }
        }
        __syncthreads();
    }
}

// ---------------- K5: per-(g,s) mean pooling via node CSR ------------------
__global__ __launch_bounds__(256)
void k5_pool() {
    int g = blockIdx.x, tid = threadIdx.x;
    __shared__ int soff[S+1];
    __shared__ unsigned short snod[NN];
    for (int i = tid; i < S+1; i += 256) soff[i] = g_noff[g*201 + i];
    for (int i = tid; i < NN; i += 256) snod[i] = g_nsrc[g*400 + i];
    __syncthreads();
    const float* xg = g_x + (size_t)g * NN * D;
    float* pg = g_pool + (size_t)g * S * D;
    int d = tid & 63;
    for (int s = tid >> 6; s < S; s += 4) {
        int b = soff[s], e2 = soff[s+1];
        float acc = 0.f;
        for (int j = b; j < e2; j++) acc += xg[(int)snod[j]*64 + d];
        int c = e2 - b;
        pg[s*64 + d] = (c > 0) ? acc / (float)c : 0.f;
    }
}

// ---------------- K6: gt_means via sparse lists + f32x2 --------------------
__global__ __launch_bounds__(256)
void k6_num() {
    int g = blockIdx.x;
    extern __shared__ float Ps[];               // 201*64
    int tid = threadIdx.x;
    const float* pg = g_pool + (size_t)g * S * D;
    for (int idx = tid; idx < 3200; idx += 256)
        ((float4*)Ps)[idx] = ((const float4*)pg)[idx];
    if (tid < 64) Ps[S*64 + tid] = 0.f;
    __syncthreads();

    int w = tid >> 5, ii = tid & 31;
    for (int e = w*50; e < w*50 + 50; e++) {
        const unsigned char* lp = g_clist + e*208;
        int len = g_clenpad[e];
        unsigned long long a0 = 0ull, a1 = 0ull;
        for (int idx = 0; idx < len; idx += 4) {
            unsigned w4 = *(const unsigned*)(lp + idx);
            int s0 =  w4        & 255;
            int s1 = (w4 >> 8)  & 255;
            int s2 = (w4 >> 16) & 255;
            int s3 =  w4 >> 24;
            unsigned long long p0 = *(const unsigned long long*)&Ps[s0*64 + 2*ii];
            unsigned long long p1 = *(const unsigned long long*)&Ps[s1*64 + 2*ii];
            unsigned long long p2 = *(const unsigned long long*)&Ps[s2*64 + 2*ii];
            unsigned long long p3 = *(const unsigned long long*)&Ps[s3*64 + 2*ii];
            ADD2(a0, a0, p0);
            ADD2(a1, a1, p1);
            ADD2(a0, a0, p2);
            ADD2(a1, a1, p3);
        }
        ADD2(a0, a0, a1);
        float lo, hi; UNPACK2(lo, hi, a0);
        float nb = g_nb[e*G + g];
        float inv = 1.f / fmaxf(nb, 1.f);
        float2 o; o.x = lo * inv; o.y = hi * inv;
        *(float2*)&g_num[((size_t)e*G + g)*64 + 2*ii] = o;
    }
}

// ---------------- K7: per-edge mean/std of gt_means ------------------------
__global__ void k7_feats(float* __restrict__ out) {
    int e = blockIdx.x, tid = threadIdx.x;
    int part = tid >> 6, d = tid & 63;
    __shared__ float sp[4][64];
    __shared__ float smean[64];
    __shared__ float red[256];

    float ln = 0.f;
    for (int g = tid; g < G; g += 256) ln += (g_nb[e*G + g] > 0.f) ? 1.f : 0.f;
    float n2 = blockReduceSum256(ln, red);

    float acc = 0.f;
    for (int g = part; g < G; g += 4) {
        if (g_nb[e*G + g] > 0.f)
            acc += g_num[((size_t)e*G + g)*64 + d];
    }
    sp[part][d] = acc;
    __syncthreads();
    if (tid < 64)
        smean[tid] = (sp[0][tid] + sp[1][tid] + sp[2][tid] + sp[3][tid]) / fmaxf(n2, 1.f);
    __syncthreads();
    float m = smean[d];

    float acc2 = 0.f;
    for (int g = part; g < G; g += 4) {
        if (g_nb[e*G + g] > 0.f) {
            float v = g_num[((size_t)e*G + g)*64 + d] - m;
            acc2 += v * v;
        }
    }
    sp[part][d] = acc2;
    __syncthreads();
    if (tid < 64) {
        float var = (sp[0][tid] + sp[1][tid] + sp[2][tid] + sp[3][tid]) / fmaxf(n2 - 1.f, 1.f);
        float sv = (n2 > 1.f) ? sqrtf(fmaxf(var, 0.f)) : 0.f;
        bool ok = (g_cmsum[e] > 0.f) && (n2 > 0.f);
        out[e*OUTC + tid]      = ok ? smean[tid] : 0.f;
        out[e*OUTC + 64 + tid] = ok ? sv : 0.f;
    }
}

// ---------------- launch ---------------------------------------------------
extern "C" void kernel_launch(void* const* d_in, const int* in_sizes, int n_in,
                              void* d_out, int out_size) {
    const int*   sids = (const int*)d_in[0];
    const void*  cmraw = d_in[3];
    const int*   ei   = (const int*)d_in[2];
    const float* emb  = (const float*)d_in[4];
    const float* W1   = (const float*)d_in[5];
    const float* b1   = (const float*)d_in[6];
    const float* W2   = (const float*)d_in[7];
    const float* b2   = (const float*)d_in[8];
    const float* eps  = (const float*)d_in[9];
    const float* gam  = (const float*)d_in[10];
    const float* bet  = (const float*)d_in[11];
    float* out = (float*)d_out;

    const int SM_K4A = NN*D*4 + (NN+1)*4 + NN*2;   // 104804
    const int SM_K4B = 43264 * 4;                  // 173056
    const int SM_K2A = 32*201*8 + 96*4;            // 51840
    const int SM_K6  = (S+1)*D*4;                  // 51456
    cudaFuncSetAttribute(k4a_agg, cudaFuncAttributeMaxDynamicSharedMemorySize, SM_K4A);
    cudaFuncSetAttribute(k4b_mlp, cudaFuncAttributeMaxDynamicSharedMemorySize, SM_K4B);
    cudaFuncSetAttribute(k2a,     cudaFuncAttributeMaxDynamicSharedMemorySize, SM_K2A);
    cudaFuncSetAttribute(k6_num,  cudaFuncAttributeMaxDynamicSharedMemorySize, SM_K6);

    // Order keeps k4b_mlp at profiler launch slot #4.
    kcsr<<<G, 512>>>(ei, sids);                                    // 1
    k4a_agg<<<G, 512, SM_K4A>>>(sids, emb, eps, 0);                // 2
    kdetect<<<1, 256>>>((const unsigned char*)cmraw);              // 3
    k4b_mlp<<<148, 256, SM_K4B>>>(W1, b1, W2, b2, gam, bet, 0);    // 4  <- profiled
    kconvert<<<(E*S + 255)/256, 256>>>(cmraw);                     // 5
    k0_build<<<E, 256>>>();                                        // 6
    k4a_agg<<<G, 512, SM_K4A>>>(sids, emb, eps, 1);                // 7
    k4b_mlp<<<148, 256, SM_K4B>>>(W1, b1, W2, b2, gam, bet, 1);    // 8
    k2a<<<(G + 31)/32, 256, SM_K2A>>>();                           // 9
    k2b<<<E, 256>>>(out);                                          // 10
    k5_pool<<<G, 256>>>();                                         // 11
    k6_num<<<G, 256, SM_K6>>>();                                   // 12
    k7_feats<<<E, 256>>>(out);                                     // 13
}

// round 13
// speedup vs baseline: 1.1225x; 1.0203x over previous
#include <cuda_runtime.h>
#include <cuda_bf16.h>
#include <cstdint>
#include <math.h>

#define G   1000
#define NN  400
#define S   200
#define E   400
#define D   64
#define TE  399
#define NT  (G*NN)
#define OUTC 138
#define TILE 256
#define NTILES ((NT + TILE - 1) / TILE)

// ---------------- packed f32x2 helpers -------------------------------------
#define FMA2(d, a, b, c) asm("fma.rn.f32x2 %0, %1, %2, %3;" : "=l"(d) : "l"(a), "l"(b), "l"(c))
#define ADD2(d, a, b)    asm("add.rn.f32x2 %0, %1, %2;"     : "=l"(d) : "l"(a), "l"(b))
#define PACK2(out, lo, hi) asm("mov.b64 %0, {%1, %2};" : "=l"(out) : "r"(__float_as_uint(lo)), "r"(__float_as_uint(hi)))
#define UNPACK2(lo, hi, in) { unsigned _ulo, _uhi; asm("mov.b64 {%0, %1}, %2;" : "=r"(_ulo), "=r"(_uhi) : "l"(in)); lo = __uint_as_float(_ulo); hi = __uint_as_float(_uhi); }

// ---------------- scratch (device globals; no allocation allowed) ----------
__device__ int      g_cm_mode;
__device__ unsigned char g_cmm[E*S];
__device__ unsigned char g_clist[E*208];   // sparse species lists (pad w/ S)
__device__ int      g_clenpad[E];
__device__ unsigned g_cmbits[E*7];
__device__ float    g_cmsum[E];
__device__ int      g_eoff[G*401];         // edge CSR offsets (by dst)
__device__ unsigned short g_esrc[G*400];   // edge CSR srcs
__device__ int      g_noff[G*201];         // node CSR offsets (by species)
__device__ unsigned short g_nsrc[G*400];   // node CSR node ids
__device__ float    g_tv[G];               // valid species per g
__device__ float    g_nb[E*G];
__device__ float    g_avgb[E*G];
__device__ float    g_cr[E*G];
__device__ float    g_fdb[E*G];
__device__ float    g_fdo[E*G];
__device__ float    g_x[NT*D];
__device__ float    g_h[NT*D];
__device__ float    g_pool[G*S*D];
__device__ float    g_num[E*G*D];

// ---------------- helpers --------------------------------------------------
__device__ __forceinline__ float blockReduceSum256(float v, float* red) {
    int tid = threadIdx.x;
    red[tid] = v; __syncthreads();
    #pragma unroll
    for (int s = 128; s > 0; s >>= 1) {
        if (tid < s) red[tid] += red[tid + s];
        __syncthreads();
    }
    float r = red[0];
    __syncthreads();
    return r;
}

// ---------------- Kd: detect clade_mask dtype ------------------------------
__global__ void kdetect(const unsigned char* __restrict__ p) {
    __shared__ int f_mis1, f_3f1, f_3f3;
    int tid = threadIdx.x;
    if (tid == 0) { f_mis1 = 0; f_3f1 = 0; f_3f3 = 0; }
    __syncthreads();
    for (int i = tid; i < E*S; i += 256) {
        unsigned char b = p[i];
        int m = i & 3;
        if (b == 1 && m != 0)    f_mis1 = 1;
        if (b == 0x3F && m == 1) f_3f1 = 1;
        if (b == 0x3F && m == 3) f_3f3 = 1;
    }
    __syncthreads();
    if (tid == 0) {
        int mode;
        if (f_mis1)      mode = 0;
        else if (f_3f1)  mode = 3;
        else if (f_3f3)  mode = 2;
        else             mode = 1;
        g_cm_mode = mode;
    }
}

__global__ void kconvert(const void* __restrict__ p) {
    int i = blockIdx.x * 256 + threadIdx.x;
    if (i >= E*S) return;
    int mode = g_cm_mode;
    bool v;
    if      (mode == 0) v = ((const unsigned char*)p)[i] != 0;
    else if (mode == 1) v = ((const int*)p)[i] != 0;
    else if (mode == 2) v = ((const float*)p)[i] != 0.f;
    else { unsigned short u = ((const unsigned short*)p)[i]; v = (unsigned short)(u << 1) != 0; }
    g_cmm[i] = v ? 1 : 0;
}

// ---------------- K0: bitmasks + deterministic sparse lists ----------------
__global__ void k0_build() {
    int e = blockIdx.x, t = threadIdx.x;
    __shared__ int wcnt[8];
    bool bit = (t < S) && g_cmm[e*S + t];
    unsigned bal = __ballot_sync(0xffffffffu, bit);
    int w = t >> 5, lane = t & 31;
    if (lane == 0) {
        wcnt[w] = __popc(bal);
        if (w < 7) g_cmbits[e*7 + w] = bal;
    }
    __syncthreads();
    int prefix = 0;
    for (int q = 0; q < w; q++) prefix += wcnt[q];
    int pos = prefix + __popc(bal & ((1u << lane) - 1u));
    if (bit) g_clist[e*208 + pos] = (unsigned char)t;
    if (t == 0) {
        int tot = 0;
        for (int q = 0; q < 8; q++) tot += wcnt[q];
        int padded = (tot + 3) & ~3;
        for (int p2 = tot; p2 < padded; p2++) g_clist[e*208 + p2] = (unsigned char)S;
        g_clenpad[e] = padded;
        g_cmsum[e] = (float)tot;
    }
}

// ---------------- Kcsr: deterministic CSRs (O(N) match_any ranks) ----------
__global__ __launch_bounds__(512)
void kcsr(const int* __restrict__ ei, const int* __restrict__ sids) {
    int g = blockIdx.x, tid = threadIdx.x;
    __shared__ int ssrc[TE], sdst[TE], ssid[NN];
    __shared__ int cnt[NN+1], off[NN+1];
    __shared__ int cnt2[S+1], off2[S+1];
    for (int i = tid; i < TE; i += 512) { ssrc[i] = ei[g*2*TE + i]; sdst[i] = ei[g*2*TE + TE + i]; }
    for (int i = tid; i < NN; i += 512) ssid[i] = sids[g*NN + i];
    for (int i = tid; i < NN+1; i += 512) cnt[i] = 0;
    for (int i = tid; i < S+1; i += 512) cnt2[i] = 0;
    __syncthreads();
    for (int i = tid; i < TE; i += 512) atomicAdd(&cnt[sdst[i]], 1);
    for (int i = tid; i < NN; i += 512) { int sd = ssid[i]; if (sd >= 0) atomicAdd(&cnt2[sd], 1); }
    __syncthreads();
    if (tid == 0) { int a = 0; for (int n2 = 0; n2 < NN; n2++) { off[n2] = a; a += cnt[n2]; } off[NN] = a; }
    if (tid == 1) { int a = 0; for (int s = 0; s < S; s++) { off2[s] = a; a += cnt2[s]; } off2[S] = a; }
    __syncthreads();
    for (int i = tid; i <= NN; i += 512) { cnt[i] = 0; g_eoff[g*401 + i] = off[i]; }
    for (int i = tid; i <= S; i += 512)  { cnt2[i] = 0; g_noff[g*201 + i] = off2[i]; }
    __syncthreads();
    int w = tid >> 5, lane = tid & 31;
    unsigned ltm = (1u << lane) - 1u;
    if (w == 0) {
        for (int base = 0; base < TE; base += 32) {
            int i = base + lane;
            bool act = i < TE;
            int key = act ? sdst[i] : NN;
            unsigned m = __match_any_sync(0xffffffffu, key);
            int prior = cnt[key];
            __syncwarp();
            if (act) g_esrc[g*400 + off[key] + prior + __popc(m & ltm)] = (unsigned short)ssrc[i];
            if (lane == (__ffs(m) - 1)) cnt[key] = prior + __popc(m);
            __syncwarp();
        }
    } else if (w == 1) {
        for (int base = 0; base < NN; base += 32) {
            int i = base + lane;
            int sd = (i < NN) ? ssid[i] : -1;
            bool act = sd >= 0;
            int key = act ? sd : S;
            unsigned m = __match_any_sync(0xffffffffu, key);
            int prior = cnt2[key];
            __syncwarp();
            if (act) g_nsrc[g*400 + off2[key] + prior + __popc(m & ltm)] = (unsigned short)i;
            if (lane == (__ffs(m) - 1)) cnt2[key] = prior + __popc(m);
            __syncwarp();
        }
    }
}

// ---------------- K2a: per-(e,g) contrast scalars (packed f32x2 scan) ------
__global__ __launch_bounds__(256)
void k2a() {
    int g0 = blockIdx.x * 32;
    int tid = threadIdx.x, lane = tid & 31, warp = tid >> 5;
    extern __shared__ float2 pc[];                 // [32][201]
    float* tvs = (float*)(pc + 32*201);
    for (int idx = tid; idx < 32*201; idx += 256) {
        int gl = idx / 201, s = idx - gl*201;
        float c = 0.f;
        int g = g0 + gl;
        if (s < S && g < G) {
            int b = g_noff[g*201 + s], e2 = g_noff[g*201 + s + 1];
            c = (float)(e2 - b);
        }
        pc[gl*201 + s] = make_float2(c, ((c > 0.f) ? 1.f : 0.f) + 4096.f * ((c > 1.f) ? 1.f : 0.f));
    }
    __syncthreads();
    if (tid < 32) {
        float tv = 0.f, tc = 0.f, td = 0.f;
        for (int s = 0; s < S; s++) {
            float2 v = pc[tid*201 + s];
            tc += v.x;
            float dup = floorf(v.y * (1.f/4096.f));
            tv += v.y - 4096.f*dup;
            td += dup;
        }
        tvs[tid] = tv; tvs[32+tid] = tc; tvs[64+tid] = td;
        if (g0 + tid < G) g_tv[g0 + tid] = tv;
    }
    __syncthreads();
    int g = g0 + lane;
    bool gok = g < G;
    float tv = tvs[lane], tc = tvs[32+lane], td = tvs[64+lane];
    const float2* prow = pc + lane*201;
    for (int e = warp; e < E; e += 8) {
        const unsigned char* lp = g_clist + e*208;
        int len = g_clenpad[e];
        unsigned long long a = 0ull;
        for (int idx = 0; idx < len; idx += 4) {
            unsigned w4 = *(const unsigned*)(lp + idx);
            unsigned long long p0 = *(const unsigned long long*)&prow[w4 & 255];
            unsigned long long p1 = *(const unsigned long long*)&prow[(w4 >> 8) & 255];
            unsigned long long p2 = *(const unsigned long long*)&prow[(w4 >> 16) & 255];
            unsigned long long p3 = *(const unsigned long long*)&prow[w4 >> 24];
            ADD2(a, a, p0); ADD2(a, a, p1); ADD2(a, a, p2); ADD2(a, a, p3);
        }
        float sb, y; UNPACK2(sb, y, a);
        float db = floorf(y * (1.f/4096.f));
        float nb = y - 4096.f*db;
        float no = tv - nb, so = tc - sb, dd = td - db;
        float avgb = __fdividef(sb, fmaxf(nb, 1.f));
        float avgo = __fdividef(so, fmaxf(no, 1.f));
        float cr   = __fdividef(avgb, fmaxf(avgo, 0.1f));
        float fdb  = __fdividef(db, fmaxf(nb, 1.f));
        float fdo  = __fdividef(dd, fmaxf(no, 1.f));
        if (gok) {
            int o = e*G + g;
            g_nb[o] = nb; g_avgb[o] = avgb; g_cr[o] = cr; g_fdb[o] = fdb; g_fdo[o] = fdo;
        }
    }
}

// ---------------- K2b: per-edge masked stats -------------------------------
__global__ void k2b(float* __restrict__ out) {
    int e = blockIdx.x, tid = threadIdx.x;
    __shared__ float sA[G], sC[G], sFb[G], sFo[G], sHf[G];
    __shared__ float red[256];
    for (int g = tid; g < G; g += 256) {
        float nb = g_nb[e*G + g];
        float tv = g_tv[g];
        sA[g] = g_avgb[e*G + g]; sC[g] = g_cr[e*G + g];
        sFb[g] = g_fdb[e*G + g]; sFo[g] = g_fdo[e*G + g];
        sHf[g] = (nb > 0.f && (tv - nb) > 0.f) ? 1.f : 0.f;
    }
    __syncthreads();
    float ln = 0.f;
    for (int g = tid; g < G; g += 256) ln += sHf[g];
    float n = blockReduceSum256(ln, red);
    float cms = g_cmsum[e];
    bool okc = (cms > 0.f) && ((float)S - cms > 0.f) && (n > 0.f);
    for (int kk = 0; kk < 5; kk++) {
        float lm = 0.f;
        for (int g = tid; g < G; g += 256) {
            float v;
            if      (kk == 0) v = sA[g];
            else if (kk == 1) v = sC[g];
            else if (kk == 2) v = sFb[g];
            else if (kk == 3) v = sFo[g];
            else              v = sFb[g] - sFo[g];
            lm += v * sHf[g];
        }
        float m = blockReduceSum256(lm, red) / fmaxf(n, 1.f);
        float lv = 0.f;
        for (int g = tid; g < G; g += 256) {
            float v;
            if      (kk == 0) v = sA[g];
            else if (kk == 1) v = sC[g];
            else if (kk == 2) v = sFb[g];
            else if (kk == 3) v = sFo[g];
            else              v = sFb[g] - sFo[g];
            float dvi = v - m;
            lv += dvi * dvi * sHf[g];
        }
        float var = blockReduceSum256(lv, red) / fmaxf(n - 1.f, 1.f);
        float sv = (n > 1.f) ? sqrtf(fmaxf(var, 0.f)) : 0.f;
        if (tid == 0) {
            out[e*OUTC + 128 + 2*kk]     = okc ? m  : 0.f;
            out[e*OUTC + 128 + 2*kk + 1] = okc ? sv : 0.f;
        }
    }
}

// ---------------- K4a: GIN aggregation via edge CSR (no atomics) -----------
__global__ __launch_bounds__(512)
void k4a_agg(const int* __restrict__ sids, const float* __restrict__ emb,
             const float* __restrict__ eps, int l) {
    int g = blockIdx.x, tid = threadIdx.x;
    extern __shared__ float sm[];
    float* xs = sm;
    int* soff = (int*)(sm + NN*D);
    unsigned short* ssrc = (unsigned short*)(soff + NN + 1);
    if (l == 0) {
        float* xg = g_x + (size_t)g * NN * D;
        for (int idx = tid; idx < NN*16; idx += 512) {
            int n2 = idx >> 4, q = idx & 15;
            int id = sids[g*NN + n2];
            if (id < 0) id = S;
            float4 v = ((const float4*)(emb + id*D))[q];
            ((float4*)xs)[idx] = v;
            ((float4*)xg)[idx] = v;
        }
    } else {
        const float* xg = g_x + (size_t)g * NN * D;
        for (int idx = tid; idx < NN*16; idx += 512)
            ((float4*)xs)[idx] = ((const float4*)xg)[idx];
    }
    for (int i = tid; i < NN+1; i += 512) soff[i] = g_eoff[g*401 + i];
    for (int i = tid; i < NN; i += 512) ssrc[i] = g_esrc[g*400 + i];
    __syncthreads();
    float e1 = 1.f + eps[l];
    int d = tid & 63;
    float* hg = g_h + (size_t)g * NN * D;
    for (int n2 = tid >> 6; n2 < NN; n2 += 8) {
        int b = soff[n2], e2 = soff[n2+1];
        float acc = 0.f;
        for (int j = b; j < e2; j++) acc += xs[(int)ssrc[j]*64 + d];
        hg[n2*64 + d] = e1 * xs[n2*64 + d] + acc;
    }
}

// ---------------- K4b: MLP + residual + LN (8x4 blocked, 512 thr) ----------
// Thread (rg = tid>>4, pg = tid&15) owns rows {rg + 32*rr : rr=0..7},
// cols 4*pg..+3 (2 f32x2 pairs). Interleaved rows keep LDS conflict-free.
// LN reduces over the 16 consecutive lanes sharing a row group.
// smem: hs[256*68] ts[256*68] Wp1[2048]f2 Wp2[2048]f2 bp1[32]f2 bp2[32]f2 gb[128]
__global__ __launch_bounds__(512, 1)
void k4b_mlp(const float* __restrict__ W1, const float* __restrict__ b1,
             const float* __restrict__ W2, const float* __restrict__ b2,
             const float* __restrict__ gam, const float* __restrict__ bet,
             int l) {
    extern __shared__ float sm[];
    float*  hs  = sm;                       // 17408 floats
    float*  ts  = sm + 17408;               // 17408
    float2* Wp1 = (float2*)(sm + 34816);    // 2048 float2
    float2* Wp2 = (float2*)(sm + 38912);    // 2048 float2
    float2* bp1 = (float2*)(sm + 43008);    // 32 float2
    float2* bp2 = (float2*)(sm + 43072);    // 32 float2
    float*  gb  = sm + 43136;               // gamma[64], beta[64]

    int tid = threadIdx.x;
    const float* W1l = W1 + l*4096;
    const float* W2l = W2 + l*4096;
    for (int idx = tid; idx < 2048; idx += 512) {
        int j = idx >> 5, p = idx & 31;
        Wp1[idx] = make_float2(W1l[(2*p)*64 + j], W1l[(2*p+1)*64 + j]);
        Wp2[idx] = make_float2(W2l[(2*p)*64 + j], W2l[(2*p+1)*64 + j]);
    }
    if (tid < 32) {
        bp1[tid] = ((const float2*)(b1 + l*64))[tid];
        bp2[tid] = ((const float2*)(b2 + l*64))[tid];
    }
    if (tid < 64) { gb[tid] = gam[l*64 + tid]; gb[64 + tid] = bet[l*64 + tid]; }

    int pg = tid & 15, rg = tid >> 4;       // rg: 0..31
    int cbase = 4 * pg;

    for (int tile = blockIdx.x; tile < NTILES; tile += gridDim.x) {
        // ---- stage hs (also first-iteration weight sync) ----
        for (int idx = tid; idx < TILE*16; idx += 512) {
            int row = idx >> 4, q = idx & 15;
            long grow = (long)tile*TILE + row;
            float4 v = make_float4(0.f, 0.f, 0.f, 0.f);
            if (grow < NT) v = *(const float4*)(g_h + grow*64 + q*4);
            *(float4*)&hs[row*68 + q*4] = v;
        }
        __syncthreads();

        // ---- GEMM1: t = relu(h @ W1^T + b1) ----
        unsigned long long acc[16];
        #pragma unroll
        for (int pp = 0; pp < 2; pp++) {
            float2 b = bp1[pg*2 + pp];
            unsigned long long bb; PACK2(bb, b.x, b.y);
            #pragma unroll
            for (int rr = 0; rr < 8; rr++) acc[rr*2 + pp] = bb;
        }
        #pragma unroll 1
        for (int jb = 0; jb < 16; jb++) {
            float4 h4[8];
            #pragma unroll
            for (int rr = 0; rr < 8; rr++)
                h4[rr] = *(const float4*)&hs[(rg + 32*rr)*68 + jb*4];
            #pragma unroll
            for (int jj = 0; jj < 4; jj++) {
                unsigned long long w2[2];
                #pragma unroll
                for (int pp = 0; pp < 2; pp++)
                    w2[pp] = *(const unsigned long long*)&Wp1[(jb*4 + jj)*32 + pg*2 + pp];
                unsigned long long hd[8];
                #pragma unroll
                for (int rr = 0; rr < 8; rr++) {
                    float hv = (jj == 0) ? h4[rr].x : (jj == 1) ? h4[rr].y : (jj == 2) ? h4[rr].z : h4[rr].w;
                    PACK2(hd[rr], hv, hv);
                }
                #pragma unroll
                for (int rr = 0; rr < 8; rr++)
                    #pragma unroll
                    for (int pp = 0; pp < 2; pp++)
                        FMA2(acc[rr*2 + pp], hd[rr], w2[pp], acc[rr*2 + pp]);
            }
        }
        // relu -> ts
        #pragma unroll
        for (int rr = 0; rr < 8; rr++)
            #pragma unroll
            for (int pp = 0; pp < 2; pp++) {
                float lo, hi; UNPACK2(lo, hi, acc[rr*2 + pp]);
                lo = fmaxf(lo, 0.f); hi = fmaxf(hi, 0.f);
                unsigned long long t2; PACK2(t2, lo, hi);
                *(unsigned long long*)&ts[(rg + 32*rr)*68 + cbase + 2*pp] = t2;
            }
        __syncthreads();

        // ---- GEMM2: y = t @ W2^T + b2 ----
        #pragma unroll
        for (int pp = 0; pp < 2; pp++) {
            float2 b = bp2[pg*2 + pp];
            unsigned long long bb; PACK2(bb, b.x, b.y);
            #pragma unroll
            for (int rr = 0; rr < 8; rr++) acc[rr*2 + pp] = bb;
        }
        #pragma unroll 1
        for (int jb = 0; jb < 16; jb++) {
            float4 h4[8];
            #pragma unroll
            for (int rr = 0; rr < 8; rr++)
                h4[rr] = *(const float4*)&ts[(rg + 32*rr)*68 + jb*4];
            #pragma unroll
            for (int jj = 0; jj < 4; jj++) {
                unsigned long long w2[2];
                #pragma unroll
                for (int pp = 0; pp < 2; pp++)
                    w2[pp] = *(const unsigned long long*)&Wp2[(jb*4 + jj)*32 + pg*2 + pp];
                unsigned long long hd[8];
                #pragma unroll
                for (int rr = 0; rr < 8; rr++) {
                    float hv = (jj == 0) ? h4[rr].x : (jj == 1) ? h4[rr].y : (jj == 2) ? h4[rr].z : h4[rr].w;
                    PACK2(hd[rr], hv, hv);
                }
                #pragma unroll
                for (int rr = 0; rr < 8; rr++)
                    #pragma unroll
                    for (int pp = 0; pp < 2; pp++)
                        FMA2(acc[rr*2 + pp], hd[rr], w2[pp], acc[rr*2 + pp]);
            }
        }

        // ---- residual + LayerNorm (16-lane reduction) ----
        #pragma unroll
        for (int rr = 0; rr < 8; rr++) {
            long grow = (long)tile*TILE + rg + 32*rr;
            bool ok = grow < NT;
            float lo[2], hi[2];
            #pragma unroll
            for (int pp = 0; pp < 2; pp++) {
                UNPACK2(lo[pp], hi[pp], acc[rr*2 + pp]);
                if (ok) {
                    float2 xv = *(const float2*)(g_x + grow*64 + cbase + 2*pp);
                    lo[pp] += xv.x; hi[pp] += xv.y;
                }
            }
            float s = lo[0] + hi[0] + lo[1] + hi[1];
            s += __shfl_xor_sync(0xffffffffu, s, 1);
            s += __shfl_xor_sync(0xffffffffu, s, 2);
            s += __shfl_xor_sync(0xffffffffu, s, 4);
            s += __shfl_xor_sync(0xffffffffu, s, 8);
            float mu = s * (1.f/64.f);
            float vs = 0.f;
            #pragma unroll
            for (int pp = 0; pp < 2; pp++) {
                float a2 = lo[pp] - mu, b2 = hi[pp] - mu;
                vs += a2*a2 + b2*b2;
            }
            vs += __shfl_xor_sync(0xffffffffu, vs, 1);
            vs += __shfl_xor_sync(0xffffffffu, vs, 2);
            vs += __shfl_xor_sync(0xffffffffu, vs, 4);
            vs += __shfl_xor_sync(0xffffffffu, vs, 8);
            float rs = rsqrtf(vs * (1.f/64.f) + 1e-5f);
            if (ok) {
                #pragma unroll
                for (int pp = 0; pp < 2; pp++) {
                    float2 gg = *(const float2*)&gb[cbase + 2*pp];
                    float2 bb2 = *(const float2*)&gb[64 + cbase + 2*pp];
                    float2 o;
                    o.x = (lo[pp] - mu) * rs * gg.x + bb2.x;
                    o.y = (hi[pp] - mu) * rs * gg.y + bb2.y;
                    *(float2*)(g_x + grow*64 + cbase + 2*pp) = o;
                }
            }
        }
        __syncthreads();
    }
}

// ---------------- K5: per-(g,s) mean pooling via node CSR ------------------
__global__ __launch_bounds__(256)
void k5_pool() {
    int g = blockIdx.x, tid = threadIdx.x;
    __shared__ int soff[S+1];
    __shared__ unsigned short snod[NN];
    for (int i = tid; i < S+1; i += 256) soff[i] = g_noff[g*201 + i];
    for (int i = tid; i < NN; i += 256) snod[i] = g_nsrc[g*400 + i];
    __syncthreads();
    const float* xg = g_x + (size_t)g * NN * D;
    float* pg = g_pool + (size_t)g * S * D;
    int d = tid & 63;
    for (int s = tid >> 6; s < S; s += 4) {
        int b = soff[s], e2 = soff[s+1];
        float acc = 0.f;
        for (int j = b; j < e2; j++) acc += xg[(int)snod[j]*64 + d];
        int c = e2 - b;
        pg[s*64 + d] = (c > 0) ? acc / (float)c : 0.f;
    }
}

// ---------------- K6: gt_means via sparse lists + f32x2 --------------------
__global__ __launch_bounds__(256)
void k6_num() {
    int g = blockIdx.x;
    extern __shared__ float Ps[];               // 201*64
    int tid = threadIdx.x;
    const float* pg = g_pool + (size_t)g * S * D;
    for (int idx = tid; idx < 3200; idx += 256)
        ((float4*)Ps)[idx] = ((const float4*)pg)[idx];
    if (tid < 64) Ps[S*64 + tid] = 0.f;
    __syncthreads();

    int w = tid >> 5, ii = tid & 31;
    for (int e = w*50; e < w*50 + 50; e++) {
        const unsigned char* lp = g_clist + e*208;
        int len = g_clenpad[e];
        unsigned long long a0 = 0ull, a1 = 0ull;
        for (int idx = 0; idx < len; idx += 4) {
            unsigned w4 = *(const unsigned*)(lp + idx);
            int s0 =  w4        & 255;
            int s1 = (w4 >> 8)  & 255;
            int s2 = (w4 >> 16) & 255;
            int s3 =  w4 >> 24;
            unsigned long long p0 = *(const unsigned long long*)&Ps[s0*64 + 2*ii];
            unsigned long long p1 = *(const unsigned long long*)&Ps[s1*64 + 2*ii];
            unsigned long long p2 = *(const unsigned long long*)&Ps[s2*64 + 2*ii];
            unsigned long long p3 = *(const unsigned long long*)&Ps[s3*64 + 2*ii];
            ADD2(a0, a0, p0);
            ADD2(a1, a1, p1);
            ADD2(a0, a0, p2);
            ADD2(a1, a1, p3);
        }
        ADD2(a0, a0, a1);
        float lo, hi; UNPACK2(lo, hi, a0);
        float nb = g_nb[e*G + g];
        float inv = 1.f / fmaxf(nb, 1.f);
        float2 o; o.x = lo * inv; o.y = hi * inv;
        *(float2*)&g_num[((size_t)e*G + g)*64 + 2*ii] = o;
    }
}

// ---------------- K7: per-edge mean/std of gt_means ------------------------
__global__ void k7_feats(float* __restrict__ out) {
    int e = blockIdx.x, tid = threadIdx.x;
    int part = tid >> 6, d = tid & 63;
    __shared__ float sp[4][64];
    __shared__ float smean[64];
    __shared__ float red[256];

    float ln = 0.f;
    for (int g = tid; g < G; g += 256) ln += (g_nb[e*G + g] > 0.f) ? 1.f : 0.f;
    float n2 = blockReduceSum256(ln, red);

    float acc = 0.f;
    for (int g = part; g < G; g += 4) {
        if (g_nb[e*G + g] > 0.f)
            acc += g_num[((size_t)e*G + g)*64 + d];
    }
    sp[part][d] = acc;
    __syncthreads();
    if (tid < 64)
        smean[tid] = (sp[0][tid] + sp[1][tid] + sp[2][tid] + sp[3][tid]) / fmaxf(n2, 1.f);
    __syncthreads();
    float m = smean[d];

    float acc2 = 0.f;
    for (int g = part; g < G; g += 4) {
        if (g_nb[e*G + g] > 0.f) {
            float v = g_num[((size_t)e*G + g)*64 + d] - m;
            acc2 += v * v;
        }
    }
    sp[part][d] = acc2;
    __syncthreads();
    if (tid < 64) {
        float var = (sp[0][tid] + sp[1][tid] + sp[2][tid] + sp[3][tid]) / fmaxf(n2 - 1.f, 1.f);
        float sv = (n2 > 1.f) ? sqrtf(fmaxf(var, 0.f)) : 0.f;
        bool ok = (g_cmsum[e] > 0.f) && (n2 > 0.f);
        out[e*OUTC + tid]      = ok ? smean[tid] : 0.f;
        out[e*OUTC + 64 + tid] = ok ? sv : 0.f;
    }
}

// ---------------- launch ---------------------------------------------------
extern "C" void kernel_launch(void* const* d_in, const int* in_sizes, int n_in,
                              void* d_out, int out_size) {
    const int*   sids = (const int*)d_in[0];
    const void*  cmraw = d_in[3];
    const int*   ei   = (const int*)d_in[2];
    const float* emb  = (const float*)d_in[4];
    const float* W1   = (const float*)d_in[5];
    const float* b1   = (const float*)d_in[6];
    const float* W2   = (const float*)d_in[7];
    const float* b2   = (const float*)d_in[8];
    const float* eps  = (const float*)d_in[9];
    const float* gam  = (const float*)d_in[10];
    const float* bet  = (const float*)d_in[11];
    float* out = (float*)d_out;

    const int SM_K4A = NN*D*4 + (NN+1)*4 + NN*2;   // 104804
    const int SM_K4B = 43264 * 4;                  // 173056
    const int SM_K2A = 32*201*8 + 96*4;            // 51840
    const int SM_K6  = (S+1)*D*4;                  // 51456
    cudaFuncSetAttribute(k4a_agg, cudaFuncAttributeMaxDynamicSharedMemorySize, SM_K4A);
    cudaFuncSetAttribute(k4b_mlp, cudaFuncAttributeMaxDynamicSharedMemorySize, SM_K4B);
    cudaFuncSetAttribute(k2a,     cudaFuncAttributeMaxDynamicSharedMemorySize, SM_K2A);
    cudaFuncSetAttribute(k6_num,  cudaFuncAttributeMaxDynamicSharedMemorySize, SM_K6);

    // Order keeps k4b_mlp at profiler launch slot #4.
    kcsr<<<G, 512>>>(ei, sids);                                    // 1
    k4a_agg<<<G, 512, SM_K4A>>>(sids, emb, eps, 0);                // 2
    kdetect<<<1, 256>>>((const unsigned char*)cmraw);              // 3
    k4b_mlp<<<148, 512, SM_K4B>>>(W1, b1, W2, b2, gam, bet, 0);    // 4  <- profiled
    kconvert<<<(E*S + 255)/256, 256>>>(cmraw);                     // 5
    k0_build<<<E, 256>>>();                                        // 6
    k4a_agg<<<G, 512, SM_K4A>>>(sids, emb, eps, 1);                // 7
    k4b_mlp<<<148, 512, SM_K4B>>>(W1, b1, W2, b2, gam, bet, 1);    // 8
    k2a<<<(G + 31)/32, 256, SM_K2A>>>();                           // 9
    k2b<<<E, 256>>>(out);                                          // 10
    k5_pool<<<G, 256>>>();                                         // 11
    k6_num<<<G, 256, SM_K6>>>();                                   // 12
    k7_feats<<<E, 256>>>(out);                                     // 13
}

// round 14
// speedup vs baseline: 1.1245x; 1.0018x over previous
#include <cuda_runtime.h>
#include <cuda_bf16.h>
#include <cstdint>
#include <math.h>

#define G   1000
#define NN  400
#define S   200
#define E   400
#define D   64
#define TE  399
#define NT  (G*NN)
#define OUTC 138
#define TILE 256
#define NTILES ((NT + TILE - 1) / TILE)

// ---------------- packed f32x2 helpers -------------------------------------
#define FMA2(d, a, b, c) asm("fma.rn.f32x2 %0, %1, %2, %3;" : "=l"(d) : "l"(a), "l"(b), "l"(c))
#define ADD2(d, a, b)    asm("add.rn.f32x2 %0, %1, %2;"     : "=l"(d) : "l"(a), "l"(b))
#define PACK2(out, lo, hi) asm("mov.b64 %0, {%1, %2};" : "=l"(out) : "r"(__float_as_uint(lo)), "r"(__float_as_uint(hi)))
#define UNPACK2(lo, hi, in) { unsigned _ulo, _uhi; asm("mov.b64 {%0, %1}, %2;" : "=r"(_ulo), "=r"(_uhi) : "l"(in)); lo = __uint_as_float(_ulo); hi = __uint_as_float(_uhi); }

// ---------------- scratch (device globals; no allocation allowed) ----------
__device__ int      g_cm_mode;
__device__ unsigned char g_cmm[E*S];
__device__ unsigned char g_clist[E*208];   // sparse species lists (pad w/ S)
__device__ int      g_clenpad[E];
__device__ unsigned g_cmbits[E*7];
__device__ float    g_cmsum[E];
__device__ int      g_eoff[G*401];         // edge CSR offsets (by dst)
__device__ unsigned short g_esrc[G*400];   // edge CSR srcs
__device__ int      g_noff[G*201];         // node CSR offsets (by species)
__device__ unsigned short g_nsrc[G*400];   // node CSR node ids
__device__ float    g_tv[G];               // valid species per g
__device__ float    g_nb[E*G];
__device__ float    g_avgb[E*G];
__device__ float    g_cr[E*G];
__device__ float    g_fdb[E*G];
__device__ float    g_fdo[E*G];
__device__ float    g_x[NT*D];
__device__ float    g_h[NT*D];
__device__ float    g_pool[G*S*D];
__device__ float    g_num[E*G*D];

// ---------------- helpers --------------------------------------------------
__device__ __forceinline__ float blockReduceSum256(float v, float* red) {
    int tid = threadIdx.x;
    red[tid] = v; __syncthreads();
    #pragma unroll
    for (int s = 128; s > 0; s >>= 1) {
        if (tid < s) red[tid] += red[tid + s];
        __syncthreads();
    }
    float r = red[0];
    __syncthreads();
    return r;
}

// ---------------- Kd: detect clade_mask dtype ------------------------------
__global__ void kdetect(const unsigned char* __restrict__ p) {
    __shared__ int f_mis1, f_3f1, f_3f3;
    int tid = threadIdx.x;
    if (tid == 0) { f_mis1 = 0; f_3f1 = 0; f_3f3 = 0; }
    __syncthreads();
    for (int i = tid; i < E*S; i += 256) {
        unsigned char b = p[i];
        int m = i & 3;
        if (b == 1 && m != 0)    f_mis1 = 1;
        if (b == 0x3F && m == 1) f_3f1 = 1;
        if (b == 0x3F && m == 3) f_3f3 = 1;
    }
    __syncthreads();
    if (tid == 0) {
        int mode;
        if (f_mis1)      mode = 0;
        else if (f_3f1)  mode = 3;
        else if (f_3f3)  mode = 2;
        else             mode = 1;
        g_cm_mode = mode;
    }
}

__global__ void kconvert(const void* __restrict__ p) {
    int i = blockIdx.x * 256 + threadIdx.x;
    if (i >= E*S) return;
    int mode = g_cm_mode;
    bool v;
    if      (mode == 0) v = ((const unsigned char*)p)[i] != 0;
    else if (mode == 1) v = ((const int*)p)[i] != 0;
    else if (mode == 2) v = ((const float*)p)[i] != 0.f;
    else { unsigned short u = ((const unsigned short*)p)[i]; v = (unsigned short)(u << 1) != 0; }
    g_cmm[i] = v ? 1 : 0;
}

// ---------------- K0: bitmasks + deterministic sparse lists ----------------
__global__ void k0_build() {
    int e = blockIdx.x, t = threadIdx.x;
    __shared__ int wcnt[8];
    bool bit = (t < S) && g_cmm[e*S + t];
    unsigned bal = __ballot_sync(0xffffffffu, bit);
    int w = t >> 5, lane = t & 31;
    if (lane == 0) {
        wcnt[w] = __popc(bal);
        if (w < 7) g_cmbits[e*7 + w] = bal;
    }
    __syncthreads();
    int prefix = 0;
    for (int q = 0; q < w; q++) prefix += wcnt[q];
    int pos = prefix + __popc(bal & ((1u << lane) - 1u));
    if (bit) g_clist[e*208 + pos] = (unsigned char)t;
    if (t == 0) {
        int tot = 0;
        for (int q = 0; q < 8; q++) tot += wcnt[q];
        int padded = (tot + 3) & ~3;
        for (int p2 = tot; p2 < padded; p2++) g_clist[e*208 + p2] = (unsigned char)S;
        g_clenpad[e] = padded;
        g_cmsum[e] = (float)tot;
    }
}

// ---------------- Kcsr: deterministic CSRs (O(N) match_any ranks) ----------
__global__ __launch_bounds__(512)
void kcsr(const int* __restrict__ ei, const int* __restrict__ sids) {
    int g = blockIdx.x, tid = threadIdx.x;
    __shared__ int ssrc[TE], sdst[TE], ssid[NN];
    __shared__ int cnt[NN+1], off[NN+1];
    __shared__ int cnt2[S+1], off2[S+1];
    for (int i = tid; i < TE; i += 512) { ssrc[i] = ei[g*2*TE + i]; sdst[i] = ei[g*2*TE + TE + i]; }
    for (int i = tid; i < NN; i += 512) ssid[i] = sids[g*NN + i];
    for (int i = tid; i < NN+1; i += 512) cnt[i] = 0;
    for (int i = tid; i < S+1; i += 512) cnt2[i] = 0;
    __syncthreads();
    for (int i = tid; i < TE; i += 512) atomicAdd(&cnt[sdst[i]], 1);
    for (int i = tid; i < NN; i += 512) { int sd = ssid[i]; if (sd >= 0) atomicAdd(&cnt2[sd], 1); }
    __syncthreads();
    if (tid == 0) { int a = 0; for (int n2 = 0; n2 < NN; n2++) { off[n2] = a; a += cnt[n2]; } off[NN] = a; }
    if (tid == 1) { int a = 0; for (int s = 0; s < S; s++) { off2[s] = a; a += cnt2[s]; } off2[S] = a; }
    __syncthreads();
    for (int i = tid; i <= NN; i += 512) { cnt[i] = 0; g_eoff[g*401 + i] = off[i]; }
    for (int i = tid; i <= S; i += 512)  { cnt2[i] = 0; g_noff[g*201 + i] = off2[i]; }
    __syncthreads();
    int w = tid >> 5, lane = tid & 31;
    unsigned ltm = (1u << lane) - 1u;
    if (w == 0) {
        for (int base = 0; base < TE; base += 32) {
            int i = base + lane;
            bool act = i < TE;
            int key = act ? sdst[i] : NN;
            unsigned m = __match_any_sync(0xffffffffu, key);
            int prior = cnt[key];
            __syncwarp();
            if (act) g_esrc[g*400 + off[key] + prior + __popc(m & ltm)] = (unsigned short)ssrc[i];
            if (lane == (__ffs(m) - 1)) cnt[key] = prior + __popc(m);
            __syncwarp();
        }
    } else if (w == 1) {
        for (int base = 0; base < NN; base += 32) {
            int i = base + lane;
            int sd = (i < NN) ? ssid[i] : -1;
            bool act = sd >= 0;
            int key = act ? sd : S;
            unsigned m = __match_any_sync(0xffffffffu, key);
            int prior = cnt2[key];
            __syncwarp();
            if (act) g_nsrc[g*400 + off2[key] + prior + __popc(m & ltm)] = (unsigned short)i;
            if (lane == (__ffs(m) - 1)) cnt2[key] = prior + __popc(m);
            __syncwarp();
        }
    }
}

// ---------------- K2a: per-(e,g) contrast scalars (packed f32x2 scan) ------
__global__ __launch_bounds__(256)
void k2a() {
    int g0 = blockIdx.x * 32;
    int tid = threadIdx.x, lane = tid & 31, warp = tid >> 5;
    extern __shared__ float2 pc[];                 // [32][201]
    float* tvs = (float*)(pc + 32*201);
    for (int idx = tid; idx < 32*201; idx += 256) {
        int gl = idx / 201, s = idx - gl*201;
        float c = 0.f;
        int g = g0 + gl;
        if (s < S && g < G) {
            int b = g_noff[g*201 + s], e2 = g_noff[g*201 + s + 1];
            c = (float)(e2 - b);
        }
        pc[gl*201 + s] = make_float2(c, ((c > 0.f) ? 1.f : 0.f) + 4096.f * ((c > 1.f) ? 1.f : 0.f));
    }
    __syncthreads();
    if (tid < 32) {
        float tv = 0.f, tc = 0.f, td = 0.f;
        for (int s = 0; s < S; s++) {
            float2 v = pc[tid*201 + s];
            tc += v.x;
            float dup = floorf(v.y * (1.f/4096.f));
            tv += v.y - 4096.f*dup;
            td += dup;
        }
        tvs[tid] = tv; tvs[32+tid] = tc; tvs[64+tid] = td;
        if (g0 + tid < G) g_tv[g0 + tid] = tv;
    }
    __syncthreads();
    int g = g0 + lane;
    bool gok = g < G;
    float tv = tvs[lane], tc = tvs[32+lane], td = tvs[64+lane];
    const float2* prow = pc + lane*201;
    for (int e = warp; e < E; e += 8) {
        const unsigned char* lp = g_clist + e*208;
        int len = g_clenpad[e];
        unsigned long long a = 0ull;
        for (int idx = 0; idx < len; idx += 4) {
            unsigned w4 = *(const unsigned*)(lp + idx);
            unsigned long long p0 = *(const unsigned long long*)&prow[w4 & 255];
            unsigned long long p1 = *(const unsigned long long*)&prow[(w4 >> 8) & 255];
            unsigned long long p2 = *(const unsigned long long*)&prow[(w4 >> 16) & 255];
            unsigned long long p3 = *(const unsigned long long*)&prow[w4 >> 24];
            ADD2(a, a, p0); ADD2(a, a, p1); ADD2(a, a, p2); ADD2(a, a, p3);
        }
        float sb, y; UNPACK2(sb, y, a);
        float db = floorf(y * (1.f/4096.f));
        float nb = y - 4096.f*db;
        float no = tv - nb, so = tc - sb, dd = td - db;
        float avgb = __fdividef(sb, fmaxf(nb, 1.f));
        float avgo = __fdividef(so, fmaxf(no, 1.f));
        float cr   = __fdividef(avgb, fmaxf(avgo, 0.1f));
        float fdb  = __fdividef(db, fmaxf(nb, 1.f));
        float fdo  = __fdividef(dd, fmaxf(no, 1.f));
        if (gok) {
            int o = e*G + g;
            g_nb[o] = nb; g_avgb[o] = avgb; g_cr[o] = cr; g_fdb[o] = fdb; g_fdo[o] = fdo;
        }
    }
}

// ---------------- K2b: per-edge masked stats -------------------------------
__global__ void k2b(float* __restrict__ out) {
    int e = blockIdx.x, tid = threadIdx.x;
    __shared__ float sA[G], sC[G], sFb[G], sFo[G], sHf[G];
    __shared__ float red[256];
    for (int g = tid; g < G; g += 256) {
        float nb = g_nb[e*G + g];
        float tv = g_tv[g];
        sA[g] = g_avgb[e*G + g]; sC[g] = g_cr[e*G + g];
        sFb[g] = g_fdb[e*G + g]; sFo[g] = g_fdo[e*G + g];
        sHf[g] = (nb > 0.f && (tv - nb) > 0.f) ? 1.f : 0.f;
    }
    __syncthreads();
    float ln = 0.f;
    for (int g = tid; g < G; g += 256) ln += sHf[g];
    float n = blockReduceSum256(ln, red);
    float cms = g_cmsum[e];
    bool okc = (cms > 0.f) && ((float)S - cms > 0.f) && (n > 0.f);
    for (int kk = 0; kk < 5; kk++) {
        float lm = 0.f;
        for (int g = tid; g < G; g += 256) {
            float v;
            if      (kk == 0) v = sA[g];
            else if (kk == 1) v = sC[g];
            else if (kk == 2) v = sFb[g];
            else if (kk == 3) v = sFo[g];
            else              v = sFb[g] - sFo[g];
            lm += v * sHf[g];
        }
        float m = blockReduceSum256(lm, red) / fmaxf(n, 1.f);
        float lv = 0.f;
        for (int g = tid; g < G; g += 256) {
            float v;
            if      (kk == 0) v = sA[g];
            else if (kk == 1) v = sC[g];
            else if (kk == 2) v = sFb[g];
            else if (kk == 3) v = sFo[g];
            else              v = sFb[g] - sFo[g];
            float dvi = v - m;
            lv += dvi * dvi * sHf[g];
        }
        float var = blockReduceSum256(lv, red) / fmaxf(n - 1.f, 1.f);
        float sv = (n > 1.f) ? sqrtf(fmaxf(var, 0.f)) : 0.f;
        if (tid == 0) {
            out[e*OUTC + 128 + 2*kk]     = okc ? m  : 0.f;
            out[e*OUTC + 128 + 2*kk + 1] = okc ? sv : 0.f;
        }
    }
}

// ---------------- K4a: GIN aggregation via edge CSR (no atomics) -----------
__global__ __launch_bounds__(512)
void k4a_agg(const int* __restrict__ sids, const float* __restrict__ emb,
             const float* __restrict__ eps, int l) {
    int g = blockIdx.x, tid = threadIdx.x;
    extern __shared__ float sm[];
    float* xs = sm;
    int* soff = (int*)(sm + NN*D);
    unsigned short* ssrc = (unsigned short*)(soff + NN + 1);
    if (l == 0) {
        float* xg = g_x + (size_t)g * NN * D;
        for (int idx = tid; idx < NN*16; idx += 512) {
            int n2 = idx >> 4, q = idx & 15;
            int id = sids[g*NN + n2];
            if (id < 0) id = S;
            float4 v = ((const float4*)(emb + id*D))[q];
            ((float4*)xs)[idx] = v;
            ((float4*)xg)[idx] = v;
        }
    } else {
        const float* xg = g_x + (size_t)g * NN * D;
        for (int idx = tid; idx < NN*16; idx += 512)
            ((float4*)xs)[idx] = ((const float4*)xg)[idx];
    }
    for (int i = tid; i < NN+1; i += 512) soff[i] = g_eoff[g*401 + i];
    for (int i = tid; i < NN; i += 512) ssrc[i] = g_esrc[g*400 + i];
    __syncthreads();
    float e1 = 1.f + eps[l];
    int d = tid & 63;
    float* hg = g_h + (size_t)g * NN * D;
    for (int n2 = tid >> 6; n2 < NN; n2 += 8) {
        int b = soff[n2], e2 = soff[n2+1];
        float acc = 0.f;
        for (int j = b; j < e2; j++) acc += xs[(int)ssrc[j]*64 + d];
        hg[n2*64 + d] = e1 * xs[n2*64 + d] + acc;
    }
}

// ---------------- K4b: MLP + residual + LN (4x4 blocked, 1024 thr) ---------
// Thread (rg = tid>>4, pg = tid&15) owns rows {rg + 64*rr : rr=0..3},
// cols 4*pg..+3 (2 f32x2 pairs). rg: 0..63. 16 consecutive lanes share a row.
// smem: hs[256*68] ts[256*68] Wp1[2048]f2 Wp2[2048]f2 bp1[32]f2 bp2[32]f2 gb[128]
__global__ __launch_bounds__(1024, 1)
void k4b_mlp(const float* __restrict__ W1, const float* __restrict__ b1,
             const float* __restrict__ W2, const float* __restrict__ b2,
             const float* __restrict__ gam, const float* __restrict__ bet,
             int l) {
    extern __shared__ float sm[];
    float*  hs  = sm;                       // 17408 floats
    float*  ts  = sm + 17408;               // 17408
    float2* Wp1 = (float2*)(sm + 34816);    // 2048 float2
    float2* Wp2 = (float2*)(sm + 38912);    // 2048 float2
    float2* bp1 = (float2*)(sm + 43008);    // 32 float2
    float2* bp2 = (float2*)(sm + 43072);    // 32 float2
    float*  gb  = sm + 43136;               // gamma[64], beta[64]

    int tid = threadIdx.x;
    const float* W1l = W1 + l*4096;
    const float* W2l = W2 + l*4096;
    for (int idx = tid; idx < 2048; idx += 1024) {
        int j = idx >> 5, p = idx & 31;
        Wp1[idx] = make_float2(W1l[(2*p)*64 + j], W1l[(2*p+1)*64 + j]);
        Wp2[idx] = make_float2(W2l[(2*p)*64 + j], W2l[(2*p+1)*64 + j]);
    }
    if (tid < 32) {
        bp1[tid] = ((const float2*)(b1 + l*64))[tid];
        bp2[tid] = ((const float2*)(b2 + l*64))[tid];
    }
    if (tid < 64) { gb[tid] = gam[l*64 + tid]; gb[64 + tid] = bet[l*64 + tid]; }

    int pg = tid & 15, rg = tid >> 4;       // rg: 0..63
    int cbase = 4 * pg;

    for (int tile = blockIdx.x; tile < NTILES; tile += gridDim.x) {
        // ---- stage hs (also first-iteration weight sync) ----
        for (int idx = tid; idx < TILE*16; idx += 1024) {
            int row = idx >> 4, q = idx & 15;
            long grow = (long)tile*TILE + row;
            float4 v = make_float4(0.f, 0.f, 0.f, 0.f);
            if (grow < NT) v = *(const float4*)(g_h + grow*64 + q*4);
            *(float4*)&hs[row*68 + q*4] = v;
        }
        __syncthreads();

        // ---- GEMM1: t = relu(h @ W1^T + b1) ----
        unsigned long long acc[8];
        #pragma unroll
        for (int pp = 0; pp < 2; pp++) {
            float2 b = bp1[pg*2 + pp];
            unsigned long long bb; PACK2(bb, b.x, b.y);
            #pragma unroll
            for (int rr = 0; rr < 4; rr++) acc[rr*2 + pp] = bb;
        }
        #pragma unroll 1
        for (int jb = 0; jb < 16; jb++) {
            float4 h4[4];
            #pragma unroll
            for (int rr = 0; rr < 4; rr++)
                h4[rr] = *(const float4*)&hs[(rg + 64*rr)*68 + jb*4];
            #pragma unroll
            for (int jj = 0; jj < 4; jj++) {
                unsigned long long w2[2];
                #pragma unroll
                for (int pp = 0; pp < 2; pp++)
                    w2[pp] = *(const unsigned long long*)&Wp1[(jb*4 + jj)*32 + pg*2 + pp];
                unsigned long long hd[4];
                #pragma unroll
                for (int rr = 0; rr < 4; rr++) {
                    float hv = (jj == 0) ? h4[rr].x : (jj == 1) ? h4[rr].y : (jj == 2) ? h4[rr].z : h4[rr].w;
                    PACK2(hd[rr], hv, hv);
                }
                #pragma unroll
                for (int rr = 0; rr < 4; rr++)
                    #pragma unroll
                    for (int pp = 0; pp < 2; pp++)
                        FMA2(acc[rr*2 + pp], hd[rr], w2[pp], acc[rr*2 + pp]);
            }
        }
        // relu -> ts
        #pragma unroll
        for (int rr = 0; rr < 4; rr++)
            #pragma unroll
            for (int pp = 0; pp < 2; pp++) {
                float lo, hi; UNPACK2(lo, hi, acc[rr*2 + pp]);
                lo = fmaxf(lo, 0.f); hi = fmaxf(hi, 0.f);
                unsigned long long t2; PACK2(t2, lo, hi);
                *(unsigned long long*)&ts[(rg + 64*rr)*68 + cbase + 2*pp] = t2;
            }
        __syncthreads();

        // ---- GEMM2: y = t @ W2^T + b2 ----
        #pragma unroll
        for (int pp = 0; pp < 2; pp++) {
            float2 b = bp2[pg*2 + pp];
            unsigned long long bb; PACK2(bb, b.x, b.y);
            #pragma unroll
            for (int rr = 0; rr < 4; rr++) acc[rr*2 + pp] = bb;
        }
        #pragma unroll 1
        for (int jb = 0; jb < 16; jb++) {
            float4 h4[4];
            #pragma unroll
            for (int rr = 0; rr < 4; rr++)
                h4[rr] = *(const float4*)&ts[(rg + 64*rr)*68 + jb*4];
            #pragma unroll
            for (int jj = 0; jj < 4; jj++) {
                unsigned long long w2[2];
                #pragma unroll
                for (int pp = 0; pp < 2; pp++)
                    w2[pp] = *(const unsigned long long*)&Wp2[(jb*4 + jj)*32 + pg*2 + pp];
                unsigned long long hd[4];
                #pragma unroll
                for (int rr = 0; rr < 4; rr++) {
                    float hv = (jj == 0) ? h4[rr].x : (jj == 1) ? h4[rr].y : (jj == 2) ? h4[rr].z : h4[rr].w;
                    PACK2(hd[rr], hv, hv);
                }
                #pragma unroll
                for (int rr = 0; rr < 4; rr++)
                    #pragma unroll
                    for (int pp = 0; pp < 2; pp++)
                        FMA2(acc[rr*2 + pp], hd[rr], w2[pp], acc[rr*2 + pp]);
            }
        }

        // ---- residual + LayerNorm (16-lane reduction) ----
        #pragma unroll
        for (int rr = 0; rr < 4; rr++) {
            long grow = (long)tile*TILE + rg + 64*rr;
            bool ok = grow < NT;
            float lo[2], hi[2];
            #pragma unroll
            for (int pp = 0; pp < 2; pp++) {
                UNPACK2(lo[pp], hi[pp], acc[rr*2 + pp]);
                if (ok) {
                    float2 xv = *(const float2*)(g_x + grow*64 + cbase + 2*pp);
                    lo[pp] += xv.x; hi[pp] += xv.y;
                }
            }
            float s = lo[0] + hi[0] + lo[1] + hi[1];
            s += __shfl_xor_sync(0xffffffffu, s, 1);
            s += __shfl_xor_sync(0xffffffffu, s, 2);
            s += __shfl_xor_sync(0xffffffffu, s, 4);
            s += __shfl_xor_sync(0xffffffffu, s, 8);
            float mu = s * (1.f/64.f);
            float vs = 0.f;
            #pragma unroll
            for (int pp = 0; pp < 2; pp++) {
                float a2 = lo[pp] - mu, b2 = hi[pp] - mu;
                vs += a2*a2 + b2*b2;
            }
            vs += __shfl_xor_sync(0xffffffffu, vs, 1);
            vs += __shfl_xor_sync(0xffffffffu, vs, 2);
            vs += __shfl_xor_sync(0xffffffffu, vs, 4);
            vs += __shfl_xor_sync(0xffffffffu, vs, 8);
            float rs = rsqrtf(vs * (1.f/64.f) + 1e-5f);
            if (ok) {
                #pragma unroll
                for (int pp = 0; pp < 2; pp++) {
                    float2 gg = *(const float2*)&gb[cbase + 2*pp];
                    float2 bb2 = *(const float2*)&gb[64 + cbase + 2*pp];
                    float2 o;
                    o.x = (lo[pp] - mu) * rs * gg.x + bb2.x;
                    o.y = (hi[pp] - mu) * rs * gg.y + bb2.y;
                    *(float2*)(g_x + grow*64 + cbase + 2*pp) = o;
                }
            }
        }
        __syncthreads();
    }
}

// ---------------- K5: per-(g,s) mean pooling via node CSR ------------------
__global__ __launch_bounds__(256)
void k5_pool() {
    int g = blockIdx.x, tid = threadIdx.x;
    __shared__ int soff[S+1];
    __shared__ unsigned short snod[NN];
    for (int i = tid; i < S+1; i += 256) soff[i] = g_noff[g*201 + i];
    for (int i = tid; i < NN; i += 256) snod[i] = g_nsrc[g*400 + i];
    __syncthreads();
    const float* xg = g_x + (size_t)g * NN * D;
    float* pg = g_pool + (size_t)g * S * D;
    int d = tid & 63;
    for (int s = tid >> 6; s < S; s += 4) {
        int b = soff[s], e2 = soff[s+1];
        float acc = 0.f;
        for (int j = b; j < e2; j++) acc += xg[(int)snod[j]*64 + d];
        int c = e2 - b;
        pg[s*64 + d] = (c > 0) ? acc / (float)c : 0.f;
    }
}

// ---------------- K6: gt_means via sparse lists + f32x2 (4 chains) ---------
__global__ __launch_bounds__(256)
void k6_num() {
    int g = blockIdx.x;
    extern __shared__ float Ps[];               // 201*64
    int tid = threadIdx.x;
    const float* pg = g_pool + (size_t)g * S * D;
    for (int idx = tid; idx < 3200; idx += 256)
        ((float4*)Ps)[idx] = ((const float4*)pg)[idx];
    if (tid < 64) Ps[S*64 + tid] = 0.f;
    __syncthreads();

    int w = tid >> 5, ii = tid & 31;
    for (int e = w*50; e < w*50 + 50; e++) {
        const unsigned char* lp = g_clist + e*208;
        int len = g_clenpad[e];
        unsigned long long a0 = 0ull, a1 = 0ull, a2 = 0ull, a3 = 0ull;
        for (int idx = 0; idx < len; idx += 4) {
            unsigned w4 = *(const unsigned*)(lp + idx);
            int s0 =  w4        & 255;
            int s1 = (w4 >> 8)  & 255;
            int s2 = (w4 >> 16) & 255;
            int s3 =  w4 >> 24;
            unsigned long long p0 = *(const unsigned long long*)&Ps[s0*64 + 2*ii];
            unsigned long long p1 = *(const unsigned long long*)&Ps[s1*64 + 2*ii];
            unsigned long long p2 = *(const unsigned long long*)&Ps[s2*64 + 2*ii];
            unsigned long long p3 = *(const unsigned long long*)&Ps[s3*64 + 2*ii];
            ADD2(a0, a0, p0);
            ADD2(a1, a1, p1);
            ADD2(a2, a2, p2);
            ADD2(a3, a3, p3);
        }
        ADD2(a0, a0, a2);
        ADD2(a1, a1, a3);
        ADD2(a0, a0, a1);
        float lo, hi; UNPACK2(lo, hi, a0);
        float nb = g_nb[e*G + g];
        float inv = 1.f / fmaxf(nb, 1.f);
        float2 o; o.x = lo * inv; o.y = hi * inv;
        *(float2*)&g_num[((size_t)e*G + g)*64 + 2*ii] = o;
    }
}

// ---------------- K7: per-edge mean/std of gt_means ------------------------
__global__ void k7_feats(float* __restrict__ out) {
    int e = blockIdx.x, tid = threadIdx.x;
    int part = tid >> 6, d = tid & 63;
    __shared__ float sp[4][64];
    __shared__ float smean[64];
    __shared__ float red[256];

    float ln = 0.f;
    for (int g = tid; g < G; g += 256) ln += (g_nb[e*G + g] > 0.f) ? 1.f : 0.f;
    float n2 = blockReduceSum256(ln, red);

    float acc = 0.f;
    for (int g = part; g < G; g += 4) {
        if (g_nb[e*G + g] > 0.f)
            acc += g_num[((size_t)e*G + g)*64 + d];
    }
    sp[part][d] = acc;
    __syncthreads();
    if (tid < 64)
        smean[tid] = (sp[0][tid] + sp[1][tid] + sp[2][tid] + sp[3][tid]) / fmaxf(n2, 1.f);
    __syncthreads();
    float m = smean[d];

    float acc2 = 0.f;
    for (int g = part; g < G; g += 4) {
        if (g_nb[e*G + g] > 0.f) {
            float v = g_num[((size_t)e*G + g)*64 + d] - m;
            acc2 += v * v;
        }
    }
    sp[part][d] = acc2;
    __syncthreads();
    if (tid < 64) {
        float var = (sp[0][tid] + sp[1][tid] + sp[2][tid] + sp[3][tid]) / fmaxf(n2 - 1.f, 1.f);
        float sv = (n2 > 1.f) ? sqrtf(fmaxf(var, 0.f)) : 0.f;
        bool ok = (g_cmsum[e] > 0.f) && (n2 > 0.f);
        out[e*OUTC + tid]      = ok ? smean[tid] : 0.f;
        out[e*OUTC + 64 + tid] = ok ? sv : 0.f;
    }
}

// ---------------- launch ---------------------------------------------------
extern "C" void kernel_launch(void* const* d_in, const int* in_sizes, int n_in,
                              void* d_out, int out_size) {
    const int*   sids = (const int*)d_in[0];
    const void*  cmraw = d_in[3];
    const int*   ei   = (const int*)d_in[2];
    const float* emb  = (const float*)d_in[4];
    const float* W1   = (const float*)d_in[5];
    const float* b1   = (const float*)d_in[6];
    const float* W2   = (const float*)d_in[7];
    const float* b2   = (const float*)d_in[8];
    const float* eps  = (const float*)d_in[9];
    const float* gam  = (const float*)d_in[10];
    const float* bet  = (const float*)d_in[11];
    float* out = (float*)d_out;

    const int SM_K4A = NN*D*4 + (NN+1)*4 + NN*2;   // 104804
    const int SM_K4B = 43264 * 4;                  // 173056
    const int SM_K2A = 32*201*8 + 96*4;            // 51840
    const int SM_K6  = (S+1)*D*4;                  // 51456
    cudaFuncSetAttribute(k4a_agg, cudaFuncAttributeMaxDynamicSharedMemorySize, SM_K4A);
    cudaFuncSetAttribute(k4b_mlp, cudaFuncAttributeMaxDynamicSharedMemorySize, SM_K4B);
    cudaFuncSetAttribute(k2a,     cudaFuncAttributeMaxDynamicSharedMemorySize, SM_K2A);
    cudaFuncSetAttribute(k6_num,  cudaFuncAttributeMaxDynamicSharedMemorySize, SM_K6);

    // Order puts k4a_agg at profiler launch slot #4 this round.
    kdetect<<<1, 256>>>((const unsigned char*)cmraw);              // 1
    kcsr<<<G, 512>>>(ei, sids);                                    // 2
    kconvert<<<(E*S + 255)/256, 256>>>(cmraw);                     // 3
    k4a_agg<<<G, 512, SM_K4A>>>(sids, emb, eps, 0);                // 4  <- profiled
    k0_build<<<E, 256>>>();                                        // 5
    k4b_mlp<<<148, 1024, SM_K4B>>>(W1, b1, W2, b2, gam, bet, 0);   // 6
    k4a_agg<<<G, 512, SM_K4A>>>(sids, emb, eps, 1);                // 7
    k4b_mlp<<<148, 1024, SM_K4B>>>(W1, b1, W2, b2, gam, bet, 1);   // 8
    k2a<<<(G + 31)/32, 256, SM_K2A>>>();                           // 9
    k2b<<<E, 256>>>(out);                                          // 10
    k5_pool<<<G, 256>>>();                                         // 11
    k6_num<<<G, 256, SM_K6>>>();                                   // 12
    k7_feats<<<E, 256>>>(out);                                     // 13
}